// round 5
// baseline (speedup 1.0000x reference)
#include <cuda_runtime.h>
#include <cuda_bf16.h>
#include <cstdint>

#define NN 50000
#define NE 800000
#define DIM 256
#define GF 200
#define NG 512

// ---------------------------------------------------------------------------
// Scratch (__device__ globals; no allocations allowed)
// ---------------------------------------------------------------------------
__device__ float g_bufA[(size_t)NN * DIM];            // hW (fp32)
__device__ float g_bufB[(size_t)NN * DIM];            // agg (fp32)
__device__ float g_bufR[(size_t)NN * DIM];            // relu(h@Wr+br)
__device__ __nv_bfloat16 g_Ah[(size_t)NN * DIM];      // h split hi
__device__ __nv_bfloat16 g_Al[(size_t)NN * DIM];      // h split lo
__device__ __nv_bfloat16 g_Ch[(size_t)NN * DIM];      // h1 split hi
__device__ __nv_bfloat16 g_Cl[(size_t)NN * DIM];      // h1 split lo
__device__ __nv_bfloat16 g_WtH[6 * DIM * DIM];        // weight slabs hi: W0,Wr0,Ri0,W1,Wr1,Ri1
__device__ __nv_bfloat16 g_WtL[6 * DIM * DIM];        // weight slabs lo
__device__ float g_T[NG * DIM];
__device__ float g_gsum[NG * GF];
__device__ int   g_cnt[NG];
// CSR scratch
__device__ int g_deg[NN];
__device__ int g_part[NN];
__device__ int g_rowptr[NN + 1];
__device__ int g_woff[NN];
__device__ int g_bsum[64];
__device__ int g_eidsrc[NE];

enum { M_DUAL = 0, M_READOUT = 1 };

__device__ __forceinline__ float relu_f(float x) { return x > 0.f ? x : 0.f; }

__device__ __forceinline__ uint32_t smem_u32(const void* p) {
    uint32_t a;
    asm("{ .reg .u64 t; cvta.to.shared.u64 t, %1; cvt.u32.u64 %0, t; }" : "=r"(a) : "l"(p));
    return a;
}
__device__ __forceinline__ uint32_t swz(uint32_t off) { return off ^ ((off >> 3) & 0x70); }
__device__ __forceinline__ void cpa16(uint32_t s, const void* g, int sz) {
    asm volatile("cp.async.cg.shared.global [%0], [%1], 16, %2;" :: "r"(s), "l"(g), "r"(sz) : "memory");
}
__device__ __forceinline__ void ldsm4(uint32_t* r, uint32_t addr) {
    asm volatile("ldmatrix.sync.aligned.m8n8.x4.shared.b16 {%0,%1,%2,%3}, [%4];"
        : "=r"(r[0]), "=r"(r[1]), "=r"(r[2]), "=r"(r[3]) : "r"(addr));
}
__device__ __forceinline__ void mma16816(float* c, const uint32_t* a, const uint32_t* b) {
    asm volatile("mma.sync.aligned.m16n8k16.row.col.f32.bf16.bf16.f32 "
        "{%0,%1,%2,%3}, {%4,%5,%6,%7}, {%8,%9}, {%0,%1,%2,%3};"
        : "+f"(c[0]), "+f"(c[1]), "+f"(c[2]), "+f"(c[3])
        : "r"(a[0]), "r"(a[1]), "r"(a[2]), "r"(a[3]), "r"(b[0]), "r"(b[1]));
}

// ---------------------------------------------------------------------------
// HMMA GEMM: BM=128, BN=128, BK=64, 512 threads (16 warps, warp tile 32x32).
// bf16x3 split: D = Ah*Bh + Al*Bh + Ah*Bl  (fp32 accum), term-major ordering.
// B slab layout: [n, k] row-major, n may span multiple concatenated matrices.
// ---------------------------------------------------------------------------
static const int SM_A = 0;                             // 2buf x 2spl x 16KB = 64KB
static const int SM_B = 4 * 16384;                     // 8 tiles x 16KB = 128KB
static const int GEMM_SMEM = SM_B + 8 * 16384 + 1024;  // 197632

template <int MODE>
__global__ __launch_bounds__(512, 1)
void gemm_tc(const __nv_bfloat16* __restrict__ Ah, const __nv_bfloat16* __restrict__ Al,
             const __nv_bfloat16* __restrict__ Bh, const __nv_bfloat16* __restrict__ Bl,
             const float* __restrict__ bias,   // DUAL: br (cols 256..511) ; READOUT: rbi
             const int* __restrict__ gid,      // READOUT
             float* __restrict__ outF,         // DUAL: bufA ; READOUT: T
             float* __restrict__ outR,         // DUAL: bufR
             int M)
{
    extern __shared__ char smem_raw[];
    uint32_t sb = (smem_u32(smem_raw) + 1023) & ~1023u;
    const int t = threadIdx.x;
    const int lane = t & 31;
    const int wid = t >> 5;
    const int rowBase = blockIdx.y * 128;
    const int colBase = blockIdx.x * 128;

    const int m0 = (wid & 3) * 32;
    const int n0 = (wid >> 2) * 32;

    const int ar = (lane & 7) + ((lane >> 3) & 1) * 8;
    const int ak = ((lane >> 4) & 1) * 8;
    const int br_ = (lane & 7) + ((lane >> 4) & 1) * 8;
    const int bk = ((lane >> 3) & 1) * 8;

    // ---- preload all B (4 chunks x 2 splits, 8192 x 16B) ----
    {
        const __nv_bfloat16* Bsrc[2] = { Bh, Bl };
        #pragma unroll 4
        for (int i = 0; i < 16; i++) {
            int idx = i * 512 + t;
            int tile = idx >> 10;                // chunk*2 + split
            int chunk = tile >> 1, split = tile & 1;
            int w = idx & 1023;
            int nrow = w >> 3, seg = w & 7;
            uint32_t sa = sb + SM_B + tile * 16384 + swz(nrow * 128 + seg * 16);
            const __nv_bfloat16* gp = Bsrc[split] + (size_t)(colBase + nrow) * 256 + chunk * 64 + seg * 8;
            cpa16(sa, gp, 16);
        }
    }
    const __nv_bfloat16* Asrc[2] = { Ah, Al };
    auto loadA = [&](int c, int buf) {
        #pragma unroll 4
        for (int i = 0; i < 4; i++) {
            int idx = i * 512 + t;               // 0..2047
            int split = idx >> 10;
            int w = idx & 1023;
            int row = w >> 3, seg = w & 7;
            int gr = rowBase + row;
            int ok = gr < M;
            uint32_t sa = sb + SM_A + (buf * 2 + split) * 16384 + swz(row * 128 + seg * 16);
            const __nv_bfloat16* gp = Asrc[split] + (size_t)(ok ? gr : 0) * 256 + c * 64 + seg * 8;
            cpa16(sa, gp, ok ? 16 : 0);
        }
    };
    loadA(0, 0);
    asm volatile("cp.async.commit_group;" ::: "memory");

    float acc[2][4][4] = {};

    #pragma unroll
    for (int c = 0; c < 4; c++) {
        if (c < 3) {
            loadA(c + 1, (c + 1) & 1);
            asm volatile("cp.async.commit_group;" ::: "memory");
            asm volatile("cp.async.wait_group 1;" ::: "memory");
        } else {
            asm volatile("cp.async.wait_group 0;" ::: "memory");
        }
        __syncthreads();

        uint32_t aH = sb + SM_A + ((c & 1) * 2 + 0) * 16384;
        uint32_t aL = aH + 16384;
        uint32_t bH = sb + SM_B + (c * 2 + 0) * 16384;
        uint32_t bL = bH + 16384;

        #pragma unroll
        for (int kk = 0; kk < 64; kk += 16) {
            uint32_t ah[2][4], al[2][4], bh[2][4], bl[2][4];
            #pragma unroll
            for (int mt = 0; mt < 2; mt++) {
                uint32_t off = swz((uint32_t)(m0 + mt * 16 + ar) * 128 + (kk + ak) * 2);
                ldsm4(ah[mt], aH + off);
                ldsm4(al[mt], aL + off);
            }
            #pragma unroll
            for (int q = 0; q < 2; q++) {
                uint32_t off = swz((uint32_t)(n0 + q * 16 + br_) * 128 + (kk + bk) * 2);
                ldsm4(bh[q], bH + off);
                ldsm4(bl[q], bL + off);
            }
            // term-major: all accs between successive hits on the same acc
            #pragma unroll
            for (int mt = 0; mt < 2; mt++)
                #pragma unroll
                for (int nt = 0; nt < 4; nt++)
                    mma16816(acc[mt][nt], ah[mt], &bh[nt >> 1][(nt & 1) * 2]);
            #pragma unroll
            for (int mt = 0; mt < 2; mt++)
                #pragma unroll
                for (int nt = 0; nt < 4; nt++)
                    mma16816(acc[mt][nt], al[mt], &bh[nt >> 1][(nt & 1) * 2]);
            #pragma unroll
            for (int mt = 0; mt < 2; mt++)
                #pragma unroll
                for (int nt = 0; nt < 4; nt++)
                    mma16816(acc[mt][nt], ah[mt], &bl[nt >> 1][(nt & 1) * 2]);
        }
        __syncthreads();
    }

    // ---- epilogue: regs -> SMEM staging (stride 129) -> coalesced global ----
    float* stg = (float*)(smem_raw + (sb + SM_B - smem_u32(smem_raw)));  // reuse B region
    #pragma unroll
    for (int mt = 0; mt < 2; mt++) {
        #pragma unroll
        for (int nt = 0; nt < 4; nt++) {
            int r = m0 + mt * 16 + (lane >> 2);
            int cc = n0 + nt * 8 + (lane & 3) * 2;
            stg[r * 129 + cc]           = acc[mt][nt][0];
            stg[r * 129 + cc + 1]       = acc[mt][nt][1];
            stg[(r + 8) * 129 + cc]     = acc[mt][nt][2];
            stg[(r + 8) * 129 + cc + 1] = acc[mt][nt][3];
        }
    }
    __syncthreads();

    const int cl = t & 127;
    const int col = colBase + cl;
    if (MODE == M_DUAL) {
        for (int row = t >> 7; row < 128; row += 4) {
            int gr = rowBase + row;
            if (gr >= M) break;
            float v = stg[row * 129 + cl];
            if (col < 256) {
                outF[(size_t)gr * 256 + col] = v;
            } else {
                outR[(size_t)gr * 256 + (col - 256)] = relu_f(v + bias[col - 256]);
            }
        }
    } else { // M_READOUT: T[gid] += relu(v + rbi), RLE over sorted gid
        int curg = -1;
        float s = 0.f;
        float bc = bias[col];
        for (int row = t >> 7; row < 128; row += 4) {
            int gr = rowBase + row;
            if (gr >= M) break;
            float v = relu_f(stg[row * 129 + cl] + bc);
            int g = gid[gr];
            if (g != curg) {
                if (curg >= 0) atomicAdd(&outF[(size_t)curg * 256 + col], s);
                curg = g; s = 0.f;
            }
            s += v;
        }
        if (curg >= 0) atomicAdd(&outF[(size_t)curg * 256 + col], s);
    }
}

// ---------------------------------------------------------------------------
// fp32 -> bf16 hi/lo split (activations)
// ---------------------------------------------------------------------------
__global__ __launch_bounds__(256)
void split_k(const float4* __restrict__ in, uint2* __restrict__ H, uint2* __restrict__ L, int n4)
{
    int i = blockIdx.x * blockDim.x + threadIdx.x;
    if (i >= n4) return;
    float4 f = in[i];
    float xs[4] = { f.x, f.y, f.z, f.w };
    union { __nv_bfloat16 b[4]; uint2 u; } hh, ll;
    #pragma unroll
    for (int j = 0; j < 4; j++) {
        __nv_bfloat16 hi = __float2bfloat16_rn(xs[j]);
        __nv_bfloat16 lo = __float2bfloat16_rn(xs[j] - __bfloat162float(hi));
        hh.b[j] = hi; ll.b[j] = lo;
    }
    H[i] = hh.u; L[i] = ll.u;
}

// All 6 weight transposes+splits in one launch: slab m: out[n*256+k]=split(Wm[k*256+n])
__global__ __launch_bounds__(256)
void wsplit_all(const float* __restrict__ w0, const float* __restrict__ w1,
                const float* __restrict__ w2, const float* __restrict__ w3,
                const float* __restrict__ w4, const float* __restrict__ w5,
                __nv_bfloat16* __restrict__ H, __nv_bfloat16* __restrict__ L)
{
    int idx = blockIdx.x * 256 + threadIdx.x;   // 0 .. 6*65536-1
    int m = idx >> 16;
    int rem = idx & 65535;
    int n = rem >> 8, k = rem & 255;
    const float* srcs[6] = { w0, w1, w2, w3, w4, w5 };
    float w = srcs[m][k * DIM + n];
    __nv_bfloat16 hi = __float2bfloat16_rn(w);
    __nv_bfloat16 lo = __float2bfloat16_rn(w - __bfloat162float(hi));
    H[idx] = hi; L[idx] = lo;
}

// ---------------------------------------------------------------------------
// CSR build + gather aggregation
// ---------------------------------------------------------------------------
__global__ void zero_i(int* p, int n)
{
    int i = blockIdx.x * blockDim.x + threadIdx.x;
    if (i < n) p[i] = 0;
}
__global__ __launch_bounds__(256)
void hist_k(const int* __restrict__ idxs, int* __restrict__ cnt, int n)
{
    int i = blockIdx.x * blockDim.x + threadIdx.x;
    if (i < n) atomicAdd(&cnt[idxs[i]], 1);
}
__global__ __launch_bounds__(1024)
void scan1_k(const int* __restrict__ deg, int* __restrict__ part, int* __restrict__ bsum)
{
    __shared__ int s[1024];
    int t = threadIdx.x;
    int idx = blockIdx.x * 1024 + t;
    int v = (idx < NN) ? deg[idx] : 0;
    s[t] = v;
    __syncthreads();
    #pragma unroll
    for (int off = 1; off < 1024; off <<= 1) {
        int x = (t >= off) ? s[t - off] : 0;
        __syncthreads();
        s[t] += x;
        __syncthreads();
    }
    if (idx < NN) part[idx] = s[t] - v;        // exclusive within block
    if (t == 1023) bsum[blockIdx.x] = s[1023];
}
__global__ void scan2_k(int* bsum, int nb)
{
    if (threadIdx.x == 0) {
        int run = 0;
        for (int i = 0; i < nb; i++) { int v = bsum[i]; bsum[i] = run; run += v; }
    }
}
__global__ __launch_bounds__(1024)
void scan3_k(const int* __restrict__ part, const int* __restrict__ bsum,
             int* __restrict__ rowptr, int* __restrict__ woff)
{
    int idx = blockIdx.x * 1024 + threadIdx.x;
    if (idx < NN) {
        int r = part[idx] + bsum[blockIdx.x];
        rowptr[idx] = r;
        woff[idx] = r;
    }
    if (idx == 0) rowptr[NN] = NE;
}
__global__ __launch_bounds__(256)
void fill_k(const int* __restrict__ src, const int* __restrict__ dst,
            int* __restrict__ woff, int* __restrict__ eidsrc, int n)
{
    int e = blockIdx.x * blockDim.x + threadIdx.x;
    if (e >= n) return;
    int pos = atomicAdd(&woff[dst[e]], 1);
    eidsrc[pos] = src[e];
}
// agg[n,:] = sum over incoming edges of hW[src,:]   (128 threads, 2 cols each)
__global__ __launch_bounds__(128)
void gather_k(const float* __restrict__ hW, const int* __restrict__ rowptr,
              const int* __restrict__ eidsrc, float* __restrict__ agg)
{
    int n = blockIdx.x;
    int t = threadIdx.x;
    int start = rowptr[n], end = rowptr[n + 1];
    float a0 = 0.f, a1 = 0.f, b0 = 0.f, b1 = 0.f;
    int j = start;
    for (; j + 1 < end; j += 2) {
        int s0 = __ldg(eidsrc + j);
        int s1 = __ldg(eidsrc + j + 1);
        a0 += hW[(size_t)s0 * 256 + t];
        a1 += hW[(size_t)s0 * 256 + t + 128];
        b0 += hW[(size_t)s1 * 256 + t];
        b1 += hW[(size_t)s1 * 256 + t + 128];
    }
    if (j < end) {
        int s0 = __ldg(eidsrc + j);
        a0 += hW[(size_t)s0 * 256 + t];
        a1 += hW[(size_t)s0 * 256 + t + 128];
    }
    agg[(size_t)n * 256 + t]       = a0 + b0;
    agg[(size_t)n * 256 + t + 128] = a1 + b1;
}

// h1 = relu(agg + b) + R   -> split to Ch/Cl
__global__ __launch_bounds__(256)
void combine_k(const float4* __restrict__ agg, const float4* __restrict__ R,
               const float* __restrict__ b, uint2* __restrict__ H, uint2* __restrict__ L, int n4)
{
    int i = blockIdx.x * blockDim.x + threadIdx.x;
    if (i >= n4) return;
    float4 a = agg[i];
    float4 r = R[i];
    int col = (i & 63) * 4;
    float4 bb = *(const float4*)(b + col);
    float vs[4] = { relu_f(a.x + bb.x) + r.x, relu_f(a.y + bb.y) + r.y,
                    relu_f(a.z + bb.z) + r.z, relu_f(a.w + bb.w) + r.w };
    union { __nv_bfloat16 q[4]; uint2 u; } hh, ll;
    #pragma unroll
    for (int j = 0; j < 4; j++) {
        __nv_bfloat16 hi = __float2bfloat16_rn(vs[j]);
        __nv_bfloat16 lo = __float2bfloat16_rn(vs[j] - __bfloat162float(hi));
        hh.q[j] = hi; ll.q[j] = lo;
    }
    H[i] = hh.u; L[i] = ll.u;
}

__global__ void zero_f4(float4* __restrict__ p, int n4)
{
    int i = blockIdx.x * blockDim.x + threadIdx.x;
    int stride = gridDim.x * blockDim.x;
    float4 z = make_float4(0.f, 0.f, 0.f, 0.f);
    for (; i < n4; i += stride) p[i] = z;
}

// gsum[g,:GF] += T[g,:256] @ Ro[256,GF] + cnt[g]*rbo
__global__ __launch_bounds__(256)
void readout_small(const float* __restrict__ T, const float* __restrict__ Ro,
                   const float* __restrict__ rbo, const int* __restrict__ cnt,
                   float* __restrict__ gsum)
{
    __shared__ float sT[DIM];
    int g = blockIdx.x;
    int t = threadIdx.x;
    sT[t] = T[(size_t)g * DIM + t];
    __syncthreads();
    if (t < GF) {
        float a = 0.f;
        #pragma unroll 8
        for (int k = 0; k < DIM; k++) a += sT[k] * Ro[k * GF + t];
        gsum[(size_t)g * GF + t] += a + (float)cnt[g] * rbo[t];
    }
}

__global__ __launch_bounds__(256)
void predict_k(const float* __restrict__ gsum, const float* __restrict__ Wp,
               const float* __restrict__ bp, float* __restrict__ out)
{
    int warp = (int)((blockIdx.x * (size_t)blockDim.x + threadIdx.x) >> 5);
    int lane = threadIdx.x & 31;
    if (warp >= NG) return;
    const float* row = gsum + (size_t)warp * GF;
    float s = 0.f;
    for (int f = lane; f < GF; f += 32) s += row[f] * Wp[f];
    #pragma unroll
    for (int o = 16; o; o >>= 1) s += __shfl_xor_sync(0xffffffffu, s, o);
    if (lane == 0) out[warp] = s + bp[0];
}

// ---------------------------------------------------------------------------
extern "C" void kernel_launch(void* const* d_in, const int* in_sizes, int n_in,
                              void* d_out, int out_size)
{
    const float* nf[2]  = { (const float*)d_in[0], (const float*)d_in[2] };
    const int*   src[2] = { (const int*)d_in[4],   (const int*)d_in[7] };
    const int*   dst[2] = { (const int*)d_in[5],   (const int*)d_in[8] };
    const int*   gid[2] = { (const int*)d_in[6],   (const int*)d_in[9] };
    const float* W[2]   = { (const float*)d_in[10], (const float*)d_in[14] };
    const float* b[2]   = { (const float*)d_in[11], (const float*)d_in[15] };
    const float* Wr[2]  = { (const float*)d_in[12], (const float*)d_in[16] };
    const float* br[2]  = { (const float*)d_in[13], (const float*)d_in[17] };
    const float* Ri[2]  = { (const float*)d_in[18], (const float*)d_in[22] };
    const float* rbi[2] = { (const float*)d_in[19], (const float*)d_in[23] };
    const float* Ro[2]  = { (const float*)d_in[20], (const float*)d_in[24] };
    const float* rbo[2] = { (const float*)d_in[21], (const float*)d_in[25] };
    const float* Wp = (const float*)d_in[26];
    const float* bp = (const float*)d_in[27];
    float* out = (float*)d_out;

    float *bufA, *bufB, *bufR, *T, *gsum;
    __nv_bfloat16 *Ahp, *Alp, *Chp, *Clp, *WtH, *WtL;
    int *cnt, *deg, *part, *rowptr, *woff, *bsum, *eidsrc;
    cudaGetSymbolAddress((void**)&bufA, g_bufA);
    cudaGetSymbolAddress((void**)&bufB, g_bufB);
    cudaGetSymbolAddress((void**)&bufR, g_bufR);
    cudaGetSymbolAddress((void**)&Ahp, g_Ah);
    cudaGetSymbolAddress((void**)&Alp, g_Al);
    cudaGetSymbolAddress((void**)&Chp, g_Ch);
    cudaGetSymbolAddress((void**)&Clp, g_Cl);
    cudaGetSymbolAddress((void**)&WtH, g_WtH);
    cudaGetSymbolAddress((void**)&WtL, g_WtL);
    cudaGetSymbolAddress((void**)&T, g_T);
    cudaGetSymbolAddress((void**)&gsum, g_gsum);
    cudaGetSymbolAddress((void**)&cnt, g_cnt);
    cudaGetSymbolAddress((void**)&deg, g_deg);
    cudaGetSymbolAddress((void**)&part, g_part);
    cudaGetSymbolAddress((void**)&rowptr, g_rowptr);
    cudaGetSymbolAddress((void**)&woff, g_woff);
    cudaGetSymbolAddress((void**)&bsum, g_bsum);
    cudaGetSymbolAddress((void**)&eidsrc, g_eidsrc);

    cudaFuncSetAttribute(gemm_tc<M_DUAL>,    cudaFuncAttributeMaxDynamicSharedMemorySize, GEMM_SMEM);
    cudaFuncSetAttribute(gemm_tc<M_READOUT>, cudaFuncAttributeMaxDynamicSharedMemorySize, GEMM_SMEM);

    const int n4 = NN * DIM / 4;
    const int NB = (NN + 1023) / 1024;       // 49 scan blocks
    const dim3 gridDual(4, (NN + 127) / 128);
    const dim3 gridRo(2, (NN + 127) / 128);

    // launch 1: all weight splits (slabs: W0,Wr0,Ri0,W1,Wr1,Ri1)
    wsplit_all<<<6 * 65536 / 256, 256>>>(W[0], Wr[0], Ri[0], W[1], Wr[1], Ri[1], WtH, WtL);
    // launch 2
    zero_f4<<<64, 256>>>((float4*)gsum, NG * GF / 4);

    for (int k = 0; k < 2; k++) {
        // 3: split h
        split_k<<<(n4 + 255) / 256, 256>>>((const float4*)nf[k], (uint2*)Ahp, (uint2*)Alp, n4);
        // 4-5: degree histogram
        zero_i<<<(NN + 255) / 256, 256>>>(deg, NN);
        hist_k<<<(NE + 255) / 256, 256>>>(dst[k], deg, NE);
        // 6: dual GEMM -> bufA (hW), bufR (relu(h@Wr+br))     [profiled launch]
        gemm_tc<M_DUAL><<<gridDual, 512, GEMM_SMEM>>>(Ahp, Alp,
            WtH + (size_t)(k * 3) * 65536, WtL + (size_t)(k * 3) * 65536,
            br[k], nullptr, bufA, bufR, NN);
        // 7-10: CSR build
        scan1_k<<<NB, 1024>>>(deg, part, bsum);
        scan2_k<<<1, 32>>>(bsum, NB);
        scan3_k<<<NB, 1024>>>(part, bsum, rowptr, woff);
        fill_k<<<(NE + 255) / 256, 256>>>(src[k], dst[k], woff, eidsrc, NE);
        // 11: gather agg = sum_in hW
        gather_k<<<NN, 128>>>(bufA, rowptr, eidsrc, bufB);
        // 12: h1 = relu(agg+b) + R -> Ch/Cl
        combine_k<<<(n4 + 255) / 256, 256>>>((const float4*)bufB, (const float4*)bufR,
                                             b[k], (uint2*)Chp, (uint2*)Clp, n4);
        // 13-14: T = segment_sum(relu(h1@Ri+rbi))
        zero_f4<<<128, 256>>>((float4*)T, NG * DIM / 4);
        gemm_tc<M_READOUT><<<gridRo, 512, GEMM_SMEM>>>(Chp, Clp,
            WtH + (size_t)(k * 3 + 2) * 65536, WtL + (size_t)(k * 3 + 2) * 65536,
            rbi[k], gid[k], T, nullptr, NN);
        // 15-17: counts + small readout into gsum
        zero_i<<<2, 256>>>(cnt, NG);
        hist_k<<<(NN + 255) / 256, 256>>>(gid[k], cnt, NN);
        readout_small<<<NG, 256>>>(T, Ro[k], rbo[k], cnt, gsum);
    }

    predict_k<<<(NG * 32 + 255) / 256, 256>>>(gsum, Wp, bp, out);
}

// round 6
// speedup vs baseline: 1.1794x; 1.1794x over previous
#include <cuda_runtime.h>
#include <cuda_fp16.h>
#include <cstdint>

#define NN 50000
#define NE 800000
#define DIM 256
#define GF 200
#define NG 512

// ---------------------------------------------------------------------------
// Scratch (__device__ globals; no allocations allowed)
// ---------------------------------------------------------------------------
__device__ float g_bufA[(size_t)NN * DIM];      // hW (fp32)
__device__ float g_bufR[(size_t)NN * DIM];      // relu(h@Wr+br)
__device__ __half g_Ah[(size_t)NN * DIM];       // h split hi
__device__ __half g_Al[(size_t)NN * DIM];       // h split lo
__device__ __half g_Ch[(size_t)NN * DIM];       // h1 split hi
__device__ __half g_Cl[(size_t)NN * DIM];       // h1 split lo
__device__ __half g_WtH[6 * DIM * DIM];         // transposed weights fp16: W0,Wr0,Ri0,W1,Wr1,Ri1
__device__ float g_T[NG * DIM];
__device__ float g_gsum[NG * GF];
__device__ int   g_cnt[NG];
// CSR scratch
__device__ int g_deg[NN];
__device__ int g_part[NN];
__device__ int g_rowptr[NN + 1];
__device__ int g_woff[NN];
__device__ int g_bsum[64];
__device__ int g_eidsrc[NE];

enum { M_DUAL = 0, M_READOUT = 1 };

__device__ __forceinline__ float relu_f(float x) { return x > 0.f ? x : 0.f; }

__device__ __forceinline__ uint32_t smem_u32(const void* p) {
    uint32_t a;
    asm("{ .reg .u64 t; cvta.to.shared.u64 t, %1; cvt.u32.u64 %0, t; }" : "=r"(a) : "l"(p));
    return a;
}
__device__ __forceinline__ uint32_t swz(uint32_t off) { return off ^ ((off >> 3) & 0x70); }
__device__ __forceinline__ void cpa16(uint32_t s, const void* g, int sz) {
    asm volatile("cp.async.cg.shared.global [%0], [%1], 16, %2;" :: "r"(s), "l"(g), "r"(sz) : "memory");
}
__device__ __forceinline__ void ldsm4(uint32_t* r, uint32_t addr) {
    asm volatile("ldmatrix.sync.aligned.m8n8.x4.shared.b16 {%0,%1,%2,%3}, [%4];"
        : "=r"(r[0]), "=r"(r[1]), "=r"(r[2]), "=r"(r[3]) : "r"(addr));
}
__device__ __forceinline__ void mma16816(float* c, const uint32_t* a, const uint32_t* b) {
    asm volatile("mma.sync.aligned.m16n8k16.row.col.f32.f16.f16.f32 "
        "{%0,%1,%2,%3}, {%4,%5,%6,%7}, {%8,%9}, {%0,%1,%2,%3};"
        : "+f"(c[0]), "+f"(c[1]), "+f"(c[2]), "+f"(c[3])
        : "r"(a[0]), "r"(a[1]), "r"(a[2]), "r"(a[3]), "r"(b[0]), "r"(b[1]));
}

// ---------------------------------------------------------------------------
// HMMA GEMM: BM=128, BN=256, BK=64. 512 threads = 16 warps, warp tile 32x64.
// fp16x2: D = Ah*Bh + Al*Bh  (fp32 accum). B fp16 single, resident in SMEM.
// B slab layout: [n, k] row-major (n spans concatenated matrices for DUAL).
// ---------------------------------------------------------------------------
static const int SM_A = 0;                              // 2buf x 2spl x 16KB = 64KB
static const int SM_B = 65536;                          // 4 chunks x 32KB = 128KB
static const int GEMM_SMEM = 65536 + 131072;            // 196608

template <int MODE>
__global__ __launch_bounds__(512, 1)
void gemm_tc(const __half* __restrict__ Ah, const __half* __restrict__ Al,
             const __half* __restrict__ Bh,
             const float* __restrict__ bias,   // DUAL: br ; READOUT: rbi
             const int* __restrict__ gid,      // READOUT
             float* __restrict__ outF,         // DUAL: bufA ; READOUT: T
             float* __restrict__ outR,         // DUAL: bufR
             int M)
{
    extern __shared__ char smem_raw[];
    uint32_t sb = smem_u32(smem_raw);
    const int t = threadIdx.x;
    const int lane = t & 31;
    const int wid = t >> 5;
    const int rowBase = blockIdx.y * 128;
    const int colBase = blockIdx.x * 256;

    const int m0 = (wid & 3) * 32;        // warp m origin
    const int n0 = (wid >> 2) * 64;       // warp n origin (4 groups of 64)

    const int ar = (lane & 7) + ((lane >> 3) & 1) * 8;
    const int ak = ((lane >> 4) & 1) * 8;
    const int br_ = (lane & 7) + ((lane >> 4) & 1) * 8;
    const int bk = ((lane >> 3) & 1) * 8;

    // ---- preload all B (4 chunks x 256 rows x 64 cols fp16 = 32KB each) ----
    #pragma unroll 4
    for (int i = 0; i < 16; i++) {
        int idx = i * 512 + t;               // 0..8191 (16B units)
        int chunk = idx >> 11;
        int w = idx & 2047;
        int nrow = w >> 3, seg = w & 7;
        uint32_t sa = sb + SM_B + chunk * 32768 + swz(nrow * 128 + seg * 16);
        const __half* gp = Bh + (size_t)(colBase + nrow) * 256 + chunk * 64 + seg * 8;
        cpa16(sa, gp, 16);
    }
    const __half* Asrc[2] = { Ah, Al };
    auto loadA = [&](int c, int buf) {
        #pragma unroll 4
        for (int i = 0; i < 4; i++) {
            int idx = i * 512 + t;           // 0..2047
            int split = idx >> 10;
            int w = idx & 1023;
            int row = w >> 3, seg = w & 7;
            int gr = rowBase + row;
            int ok = gr < M;
            uint32_t sa = sb + SM_A + (buf * 2 + split) * 16384 + swz(row * 128 + seg * 16);
            const __half* gp = Asrc[split] + (size_t)(ok ? gr : 0) * 256 + c * 64 + seg * 8;
            cpa16(sa, gp, ok ? 16 : 0);
        }
    };
    loadA(0, 0);
    asm volatile("cp.async.commit_group;" ::: "memory");

    float acc[2][8][4] = {};

    #pragma unroll
    for (int c = 0; c < 4; c++) {
        if (c < 3) {
            loadA(c + 1, (c + 1) & 1);
            asm volatile("cp.async.commit_group;" ::: "memory");
            asm volatile("cp.async.wait_group 1;" ::: "memory");
        } else {
            asm volatile("cp.async.wait_group 0;" ::: "memory");
        }
        __syncthreads();

        uint32_t aH = sb + SM_A + ((c & 1) * 2 + 0) * 16384;
        uint32_t aL = aH + 16384;
        uint32_t bB = sb + SM_B + c * 32768;

        #pragma unroll
        for (int kk = 0; kk < 64; kk += 16) {
            uint32_t ah[2][4], al[2][4], bh[4][4];
            #pragma unroll
            for (int mt = 0; mt < 2; mt++) {
                uint32_t off = swz((uint32_t)(m0 + mt * 16 + ar) * 128 + (kk + ak) * 2);
                ldsm4(ah[mt], aH + off);
                ldsm4(al[mt], aL + off);
            }
            #pragma unroll
            for (int q = 0; q < 4; q++) {
                uint32_t off = swz((uint32_t)(n0 + q * 16 + br_) * 128 + (kk + bk) * 2);
                ldsm4(bh[q], bB + off);
            }
            // term-major: hi term over all 16 accs, then lo term
            #pragma unroll
            for (int mt = 0; mt < 2; mt++)
                #pragma unroll
                for (int nt = 0; nt < 8; nt++)
                    mma16816(acc[mt][nt], ah[mt], &bh[nt >> 1][(nt & 1) * 2]);
            #pragma unroll
            for (int mt = 0; mt < 2; mt++)
                #pragma unroll
                for (int nt = 0; nt < 8; nt++)
                    mma16816(acc[mt][nt], al[mt], &bh[nt >> 1][(nt & 1) * 2]);
        }
        __syncthreads();
    }

    // ---- epilogue: regs -> SMEM staging (128 x 256, stride 257) ----
    float* stg = (float*)smem_raw;   // reuse all smem
    #pragma unroll
    for (int mt = 0; mt < 2; mt++) {
        #pragma unroll
        for (int nt = 0; nt < 8; nt++) {
            int r = m0 + mt * 16 + (lane >> 2);
            int cc = n0 + nt * 8 + (lane & 3) * 2;
            stg[r * 257 + cc]           = acc[mt][nt][0];
            stg[r * 257 + cc + 1]       = acc[mt][nt][1];
            stg[(r + 8) * 257 + cc]     = acc[mt][nt][2];
            stg[(r + 8) * 257 + cc + 1] = acc[mt][nt][3];
        }
    }
    __syncthreads();

    const int cl = t & 255;
    const int col = colBase + cl;
    if (MODE == M_DUAL) {
        for (int row = t >> 8; row < 128; row += 2) {
            int gr = rowBase + row;
            if (gr >= M) break;
            float v = stg[row * 257 + cl];
            if (col < 256) {
                outF[(size_t)gr * 256 + col] = v;
            } else {
                outR[(size_t)gr * 256 + (col - 256)] = relu_f(v + bias[col - 256]);
            }
        }
    } else { // M_READOUT: T[gid] += relu(v + rbi), RLE over sorted gid
        int curg = -1;
        float s = 0.f;
        float bc = bias[col];
        for (int row = t >> 8; row < 128; row += 2) {
            int gr = rowBase + row;
            if (gr >= M) break;
            float v = relu_f(stg[row * 257 + cl] + bc);
            int g = gid[gr];
            if (g != curg) {
                if (curg >= 0) atomicAdd(&outF[(size_t)curg * 256 + col], s);
                curg = g; s = 0.f;
            }
            s += v;
        }
        if (curg >= 0) atomicAdd(&outF[(size_t)curg * 256 + col], s);
    }
}

// ---------------------------------------------------------------------------
// fp32 -> fp16 hi/lo split (activations)
// ---------------------------------------------------------------------------
__global__ __launch_bounds__(256)
void split_k(const float4* __restrict__ in, uint2* __restrict__ H, uint2* __restrict__ L, int n4)
{
    int i = blockIdx.x * blockDim.x + threadIdx.x;
    if (i >= n4) return;
    float4 f = in[i];
    float xs[4] = { f.x, f.y, f.z, f.w };
    union { __half h[4]; uint2 u; } hh, ll;
    #pragma unroll
    for (int j = 0; j < 4; j++) {
        __half hi = __float2half_rn(xs[j]);
        __half lo = __float2half_rn(xs[j] - __half2float(hi));
        hh.h[j] = hi; ll.h[j] = lo;
    }
    H[i] = hh.u; L[i] = ll.u;
}

// All 6 weight transposes in one launch: slab m: out[n*256+k] = fp16(Wm[k*256+n])
__global__ __launch_bounds__(256)
void wsplit_all(const float* __restrict__ w0, const float* __restrict__ w1,
                const float* __restrict__ w2, const float* __restrict__ w3,
                const float* __restrict__ w4, const float* __restrict__ w5,
                __half* __restrict__ H)
{
    int idx = blockIdx.x * 256 + threadIdx.x;   // 0 .. 6*65536-1
    int m = idx >> 16;
    int rem = idx & 65535;
    int n = rem >> 8, k = rem & 255;
    const float* srcs[6] = { w0, w1, w2, w3, w4, w5 };
    H[idx] = __float2half_rn(srcs[m][k * DIM + n]);
}

// ---------------------------------------------------------------------------
// CSR build
// ---------------------------------------------------------------------------
__global__ void zero_i(int* p, int n)
{
    int i = blockIdx.x * blockDim.x + threadIdx.x;
    if (i < n) p[i] = 0;
}
__global__ __launch_bounds__(256)
void hist_k(const int* __restrict__ idxs, int* __restrict__ cnt, int n)
{
    int i = blockIdx.x * blockDim.x + threadIdx.x;
    if (i < n) atomicAdd(&cnt[idxs[i]], 1);
}
__global__ __launch_bounds__(1024)
void scan1_k(const int* __restrict__ deg, int* __restrict__ part, int* __restrict__ bsum)
{
    __shared__ int s[1024];
    int t = threadIdx.x;
    int idx = blockIdx.x * 1024 + t;
    int v = (idx < NN) ? deg[idx] : 0;
    s[t] = v;
    __syncthreads();
    #pragma unroll
    for (int off = 1; off < 1024; off <<= 1) {
        int x = (t >= off) ? s[t - off] : 0;
        __syncthreads();
        s[t] += x;
        __syncthreads();
    }
    if (idx < NN) part[idx] = s[t] - v;
    if (t == 1023) bsum[blockIdx.x] = s[1023];
}
__global__ void scan2_k(int* bsum, int nb)
{
    if (threadIdx.x == 0) {
        int run = 0;
        for (int i = 0; i < nb; i++) { int v = bsum[i]; bsum[i] = run; run += v; }
    }
}
__global__ __launch_bounds__(1024)
void scan3_k(const int* __restrict__ part, const int* __restrict__ bsum,
             int* __restrict__ rowptr, int* __restrict__ woff)
{
    int idx = blockIdx.x * 1024 + threadIdx.x;
    if (idx < NN) {
        int r = part[idx] + bsum[blockIdx.x];
        rowptr[idx] = r;
        woff[idx] = r;
    }
    if (idx == 0) rowptr[NN] = NE;
}
__global__ __launch_bounds__(256)
void fill_k(const int* __restrict__ src, const int* __restrict__ dst,
            int* __restrict__ woff, int* __restrict__ eidsrc, int n)
{
    int e = blockIdx.x * blockDim.x + threadIdx.x;
    if (e >= n) return;
    int pos = atomicAdd(&woff[dst[e]], 1);
    eidsrc[pos] = src[e];
}

// ---------------------------------------------------------------------------
// Fused gather + combine: agg = sum_in hW; h1 = relu(agg+b) + R -> Ch/Cl fp16
// 128 threads/node, thread t owns cols {2t, 2t+1} (float2 lane).
// ---------------------------------------------------------------------------
__global__ __launch_bounds__(128)
void gather_combine_k(const float2* __restrict__ hW2, const int* __restrict__ rowptr,
                      const int* __restrict__ eidsrc, const float2* __restrict__ R2,
                      const float* __restrict__ bvec,
                      __half2* __restrict__ H2, __half2* __restrict__ L2)
{
    int n = blockIdx.x;
    int t = threadIdx.x;
    int start = rowptr[n], end = rowptr[n + 1];
    float ax = 0.f, ay = 0.f, bx = 0.f, by = 0.f;
    int j = start;
    for (; j + 1 < end; j += 2) {
        int s0 = __ldg(eidsrc + j);
        int s1 = __ldg(eidsrc + j + 1);
        float2 v0 = hW2[(size_t)s0 * 128 + t];
        float2 v1 = hW2[(size_t)s1 * 128 + t];
        ax += v0.x; ay += v0.y;
        bx += v1.x; by += v1.y;
    }
    if (j < end) {
        int s0 = __ldg(eidsrc + j);
        float2 v0 = hW2[(size_t)s0 * 128 + t];
        ax += v0.x; ay += v0.y;
    }
    ax += bx; ay += by;
    float2 bb = ((const float2*)bvec)[t];
    float2 r = R2[(size_t)n * 128 + t];
    float v0 = relu_f(ax + bb.x) + r.x;
    float v1 = relu_f(ay + bb.y) + r.y;
    __half h0 = __float2half_rn(v0);
    __half h1 = __float2half_rn(v1);
    __half l0 = __float2half_rn(v0 - __half2float(h0));
    __half l1 = __float2half_rn(v1 - __half2float(h1));
    H2[(size_t)n * 128 + t] = __halves2half2(h0, h1);
    L2[(size_t)n * 128 + t] = __halves2half2(l0, l1);
}

__global__ void zero_f4(float4* __restrict__ p, int n4)
{
    int i = blockIdx.x * blockDim.x + threadIdx.x;
    int stride = gridDim.x * blockDim.x;
    float4 z = make_float4(0.f, 0.f, 0.f, 0.f);
    for (; i < n4; i += stride) p[i] = z;
}

// gsum[g,:GF] += T[g,:256] @ Ro[256,GF] + cnt[g]*rbo
__global__ __launch_bounds__(256)
void readout_small(const float* __restrict__ T, const float* __restrict__ Ro,
                   const float* __restrict__ rbo, const int* __restrict__ cnt,
                   float* __restrict__ gsum)
{
    __shared__ float sT[DIM];
    int g = blockIdx.x;
    int t = threadIdx.x;
    sT[t] = T[(size_t)g * DIM + t];
    __syncthreads();
    if (t < GF) {
        float a = 0.f;
        #pragma unroll 8
        for (int k = 0; k < DIM; k++) a += sT[k] * Ro[k * GF + t];
        gsum[(size_t)g * GF + t] += a + (float)cnt[g] * rbo[t];
    }
}

__global__ __launch_bounds__(256)
void predict_k(const float* __restrict__ gsum, const float* __restrict__ Wp,
               const float* __restrict__ bp, float* __restrict__ out)
{
    int warp = (int)((blockIdx.x * (size_t)blockDim.x + threadIdx.x) >> 5);
    int lane = threadIdx.x & 31;
    if (warp >= NG) return;
    const float* row = gsum + (size_t)warp * GF;
    float s = 0.f;
    for (int f = lane; f < GF; f += 32) s += row[f] * Wp[f];
    #pragma unroll
    for (int o = 16; o; o >>= 1) s += __shfl_xor_sync(0xffffffffu, s, o);
    if (lane == 0) out[warp] = s + bp[0];
}

// ---------------------------------------------------------------------------
extern "C" void kernel_launch(void* const* d_in, const int* in_sizes, int n_in,
                              void* d_out, int out_size)
{
    const float* nf[2]  = { (const float*)d_in[0], (const float*)d_in[2] };
    const int*   src[2] = { (const int*)d_in[4],   (const int*)d_in[7] };
    const int*   dst[2] = { (const int*)d_in[5],   (const int*)d_in[8] };
    const int*   gid[2] = { (const int*)d_in[6],   (const int*)d_in[9] };
    const float* W[2]   = { (const float*)d_in[10], (const float*)d_in[14] };
    const float* b[2]   = { (const float*)d_in[11], (const float*)d_in[15] };
    const float* Wr[2]  = { (const float*)d_in[12], (const float*)d_in[16] };
    const float* br[2]  = { (const float*)d_in[13], (const float*)d_in[17] };
    const float* Ri[2]  = { (const float*)d_in[18], (const float*)d_in[22] };
    const float* rbi[2] = { (const float*)d_in[19], (const float*)d_in[23] };
    const float* Ro[2]  = { (const float*)d_in[20], (const float*)d_in[24] };
    const float* rbo[2] = { (const float*)d_in[21], (const float*)d_in[25] };
    const float* Wp = (const float*)d_in[26];
    const float* bp = (const float*)d_in[27];
    float* out = (float*)d_out;

    float *bufA, *bufR, *T, *gsum;
    __half *Ahp, *Alp, *Chp, *Clp, *WtH;
    int *cnt, *deg, *part, *rowptr, *woff, *bsum, *eidsrc;
    cudaGetSymbolAddress((void**)&bufA, g_bufA);
    cudaGetSymbolAddress((void**)&bufR, g_bufR);
    cudaGetSymbolAddress((void**)&Ahp, g_Ah);
    cudaGetSymbolAddress((void**)&Alp, g_Al);
    cudaGetSymbolAddress((void**)&Chp, g_Ch);
    cudaGetSymbolAddress((void**)&Clp, g_Cl);
    cudaGetSymbolAddress((void**)&WtH, g_WtH);
    cudaGetSymbolAddress((void**)&T, g_T);
    cudaGetSymbolAddress((void**)&gsum, g_gsum);
    cudaGetSymbolAddress((void**)&cnt, g_cnt);
    cudaGetSymbolAddress((void**)&deg, g_deg);
    cudaGetSymbolAddress((void**)&part, g_part);
    cudaGetSymbolAddress((void**)&rowptr, g_rowptr);
    cudaGetSymbolAddress((void**)&woff, g_woff);
    cudaGetSymbolAddress((void**)&bsum, g_bsum);
    cudaGetSymbolAddress((void**)&eidsrc, g_eidsrc);

    cudaFuncSetAttribute(gemm_tc<M_DUAL>,    cudaFuncAttributeMaxDynamicSharedMemorySize, GEMM_SMEM);
    cudaFuncSetAttribute(gemm_tc<M_READOUT>, cudaFuncAttributeMaxDynamicSharedMemorySize, GEMM_SMEM);

    const int n4 = NN * DIM / 4;
    const int NB = (NN + 1023) / 1024;
    const dim3 gridDual(2, (NN + 127) / 128);   // BN=256 covers [W;Wr]
    const dim3 gridRo(1, (NN + 127) / 128);

    // 1: weight transposes (fp16)
    wsplit_all<<<6 * 65536 / 256, 256>>>(W[0], Wr[0], Ri[0], W[1], Wr[1], Ri[1], WtH);
    // 2: zero gsum
    zero_f4<<<64, 256>>>((float4*)gsum, NG * GF / 4);

    for (int k = 0; k < 2; k++) {
        // 3: split h -> Ah/Al
        split_k<<<(n4 + 255) / 256, 256>>>((const float4*)nf[k], (uint2*)Ahp, (uint2*)Alp, n4);
        // 4: dual GEMM -> bufA (hW), bufR (relu(h@Wr+br))   [ncu-profiled slot]
        gemm_tc<M_DUAL><<<gridDual, 512, GEMM_SMEM>>>(Ahp, Alp,
            WtH + (size_t)(k * 3) * 65536, br[k], nullptr, bufA, bufR, NN);
        // 5-10: CSR build
        zero_i<<<(NN + 255) / 256, 256>>>(deg, NN);
        hist_k<<<(NE + 255) / 256, 256>>>(dst[k], deg, NE);
        scan1_k<<<NB, 1024>>>(deg, part, bsum);
        scan2_k<<<1, 32>>>(bsum, NB);
        scan3_k<<<NB, 1024>>>(part, bsum, rowptr, woff);
        fill_k<<<(NE + 255) / 256, 256>>>(src[k], dst[k], woff, eidsrc, NE);
        // 11: fused gather+combine -> Ch/Cl
        gather_combine_k<<<NN, 128>>>((const float2*)bufA, rowptr, eidsrc,
                                      (const float2*)bufR, b[k],
                                      (__half2*)Chp, (__half2*)Clp);
        // 12-13: T = segment_sum(relu(h1@Ri+rbi))
        zero_f4<<<128, 256>>>((float4*)T, NG * DIM / 4);
        gemm_tc<M_READOUT><<<gridRo, 512, GEMM_SMEM>>>(Chp, Clp,
            WtH + (size_t)(k * 3 + 2) * 65536, rbi[k], gid[k], T, nullptr, NN);
        // 14-16: counts + small readout into gsum
        zero_i<<<2, 256>>>(cnt, NG);
        hist_k<<<(NN + 255) / 256, 256>>>(gid[k], cnt, NN);
        readout_small<<<NG, 256>>>(T, Ro[k], rbo[k], cnt, gsum);
    }

    predict_k<<<(NG * 32 + 255) / 256, 256>>>(gsum, Wp, bp, out);
}

// round 7
// speedup vs baseline: 1.7737x; 1.5039x over previous
#include <cuda_runtime.h>
#include <cuda_fp16.h>
#include <cstdint>

#define NN 50000
#define NE 800000
#define DIM 256
#define GF 200
#define NG 512

// ---------------------------------------------------------------------------
// Scratch (__device__ globals; no allocations allowed)
// ---------------------------------------------------------------------------
__device__ float g_bufA[(size_t)NN * DIM];      // hW (fp32)
__device__ float g_bufR[(size_t)NN * DIM];      // relu(h@Wr+br)
__device__ __half g_Ah[(size_t)NN * DIM];       // h split hi
__device__ __half g_Al[(size_t)NN * DIM];       // h split lo
__device__ __half g_Ch[(size_t)NN * DIM];       // h1 split hi
__device__ __half g_Cl[(size_t)NN * DIM];       // h1 split lo
__device__ __half g_WtH[6 * DIM * DIM];         // transposed weights fp16
__device__ float g_T[NG * DIM];
__device__ float g_gsum[NG * GF];
__device__ int   g_cnt[NG];
// CSR scratch
__device__ int g_deg[NN];
__device__ int g_part[NN];
__device__ int g_rowptr[NN + 1];
__device__ int g_woff[NN];
__device__ int g_bsum[64];
__device__ int g_eidsrc[NE];

enum { M_DUAL = 0, M_READOUT = 1 };

__device__ __forceinline__ float relu_f(float x) { return x > 0.f ? x : 0.f; }

__device__ __forceinline__ uint32_t smem_u32(const void* p) {
    uint32_t a;
    asm("{ .reg .u64 t; cvta.to.shared.u64 t, %1; cvt.u32.u64 %0, t; }" : "=r"(a) : "l"(p));
    return a;
}
__device__ __forceinline__ uint32_t swz(uint32_t off) { return off ^ ((off >> 3) & 0x70); }
__device__ __forceinline__ void cpa16(uint32_t s, const void* g, int sz) {
    asm volatile("cp.async.cg.shared.global [%0], [%1], 16, %2;" :: "r"(s), "l"(g), "r"(sz) : "memory");
}
__device__ __forceinline__ void ldsm4(uint32_t* r, uint32_t addr) {
    asm volatile("ldmatrix.sync.aligned.m8n8.x4.shared.b16 {%0,%1,%2,%3}, [%4];"
        : "=r"(r[0]), "=r"(r[1]), "=r"(r[2]), "=r"(r[3]) : "r"(addr));
}
__device__ __forceinline__ void mma16816(float* c, const uint32_t* a, const uint32_t* b) {
    asm volatile("mma.sync.aligned.m16n8k16.row.col.f32.f16.f16.f32 "
        "{%0,%1,%2,%3}, {%4,%5,%6,%7}, {%8,%9}, {%0,%1,%2,%3};"
        : "+f"(c[0]), "+f"(c[1]), "+f"(c[2]), "+f"(c[3])
        : "r"(a[0]), "r"(a[1]), "r"(a[2]), "r"(a[3]), "r"(b[0]), "r"(b[1]));
}

// ---------------------------------------------------------------------------
// HMMA GEMM: BM=128, BN=128, BK=64. 256 threads = 8 warps, warp tile 32x64.
// fp16x2: D = Ah*Bh + Al*Bh (fp32 accum). A and B double-buffered.
// 2 CTAs/SM (96KB smem, 128 regs). B slab layout: [n, k] row-major.
// ---------------------------------------------------------------------------
static const int SM_A = 0;                 // 2buf x 2split x 16KB = 64KB
static const int SM_B = 65536;             // 2buf x 16KB = 32KB
static const int GEMM_SMEM = 98304;        // 96KB

template <int MODE>
__global__ __launch_bounds__(256, 2)
void gemm_tc(const __half* __restrict__ Ah, const __half* __restrict__ Al,
             const __half* __restrict__ Bh,
             const float* __restrict__ bias,   // DUAL: br ; READOUT: rbi
             const int* __restrict__ gid,      // READOUT
             float* __restrict__ outF,         // DUAL: bufA ; READOUT: T
             float* __restrict__ outR,         // DUAL: bufR
             int M)
{
    extern __shared__ char smem_raw[];
    uint32_t sb = smem_u32(smem_raw);
    const int t = threadIdx.x;
    const int lane = t & 31;
    const int wid = t >> 5;
    const int rowBase = blockIdx.y * 128;
    const int colBase = blockIdx.x * 128;

    const int m0 = (wid & 3) * 32;        // warp m origin (4 m-groups)
    const int n0 = (wid >> 2) * 64;       // warp n origin (2 n-groups)

    const int ar = (lane & 7) + ((lane >> 3) & 1) * 8;
    const int ak = ((lane >> 4) & 1) * 8;
    const int br_ = (lane & 7) + ((lane >> 4) & 1) * 8;
    const int bk = ((lane >> 3) & 1) * 8;

    // loop-invariant swizzled bases (kk folds in via XOR: swz(x+kk*2)=swz(x)^(kk*2))
    uint32_t aRel[2], bRel[4];
    #pragma unroll
    for (int mt = 0; mt < 2; mt++)
        aRel[mt] = swz((uint32_t)(m0 + mt * 16 + ar) * 128 + ak * 2);
    #pragma unroll
    for (int q = 0; q < 4; q++)
        bRel[q] = swz((uint32_t)(n0 + q * 16 + br_) * 128 + bk * 2);

    const __half* Asrc[2] = { Ah, Al };
    auto loadAB = [&](int c, int buf) {
        // A: 2 splits x 128 rows x 64 cols fp16 = 2048 16B units (8/thread)
        #pragma unroll
        for (int i = 0; i < 8; i++) {
            int idx = i * 256 + t;
            int split = idx >> 10;
            int w = idx & 1023;
            int row = w >> 3, seg = w & 7;
            int gr = rowBase + row;
            int ok = gr < M;
            uint32_t sa = sb + SM_A + (buf * 2 + split) * 16384 + swz(row * 128 + seg * 16);
            const __half* gp = Asrc[split] + (size_t)(ok ? gr : 0) * 256 + c * 64 + seg * 8;
            cpa16(sa, gp, ok ? 16 : 0);
        }
        // B: 128 rows x 64 cols fp16 = 1024 units (4/thread)
        #pragma unroll
        for (int i = 0; i < 4; i++) {
            int idx = i * 256 + t;
            int row = idx >> 3, seg = idx & 7;
            uint32_t sa = sb + SM_B + buf * 16384 + swz(row * 128 + seg * 16);
            const __half* gp = Bh + (size_t)(colBase + row) * 256 + c * 64 + seg * 8;
            cpa16(sa, gp, 16);
        }
    };
    loadAB(0, 0);
    asm volatile("cp.async.commit_group;" ::: "memory");

    float acc[2][8][4] = {};

    #pragma unroll
    for (int c = 0; c < 4; c++) {
        if (c < 3) {
            loadAB(c + 1, (c + 1) & 1);
            asm volatile("cp.async.commit_group;" ::: "memory");
            asm volatile("cp.async.wait_group 1;" ::: "memory");
        } else {
            asm volatile("cp.async.wait_group 0;" ::: "memory");
        }
        __syncthreads();

        uint32_t aH = sb + SM_A + ((c & 1) * 2 + 0) * 16384;
        uint32_t aL = aH + 16384;
        uint32_t bB = sb + SM_B + (c & 1) * 16384;

        #pragma unroll
        for (int kk2 = 0; kk2 < 128; kk2 += 32) {   // kk*2 byte offset
            uint32_t ah[2][4], al[2][4], bh[4][4];
            #pragma unroll
            for (int mt = 0; mt < 2; mt++) {
                ldsm4(ah[mt], aH + (aRel[mt] ^ kk2));
                ldsm4(al[mt], aL + (aRel[mt] ^ kk2));
            }
            #pragma unroll
            for (int q = 0; q < 4; q++)
                ldsm4(bh[q], bB + (bRel[q] ^ kk2));
            // term-major: hi term over all 16 accs, then lo term
            #pragma unroll
            for (int mt = 0; mt < 2; mt++)
                #pragma unroll
                for (int nt = 0; nt < 8; nt++)
                    mma16816(acc[mt][nt], ah[mt], &bh[nt >> 1][(nt & 1) * 2]);
            #pragma unroll
            for (int mt = 0; mt < 2; mt++)
                #pragma unroll
                for (int nt = 0; nt < 8; nt++)
                    mma16816(acc[mt][nt], al[mt], &bh[nt >> 1][(nt & 1) * 2]);
        }
        __syncthreads();
    }

    // ---- epilogue: regs -> SMEM staging (128 x 128, stride 129) ----
    float* stg = (float*)smem_raw;
    #pragma unroll
    for (int mt = 0; mt < 2; mt++) {
        #pragma unroll
        for (int nt = 0; nt < 8; nt++) {
            int r = m0 + mt * 16 + (lane >> 2);
            int cc = n0 + nt * 8 + (lane & 3) * 2;
            stg[r * 129 + cc]           = acc[mt][nt][0];
            stg[r * 129 + cc + 1]       = acc[mt][nt][1];
            stg[(r + 8) * 129 + cc]     = acc[mt][nt][2];
            stg[(r + 8) * 129 + cc + 1] = acc[mt][nt][3];
        }
    }
    __syncthreads();

    const int cl = t & 127;
    const int col = colBase + cl;
    if (MODE == M_DUAL) {
        for (int row = t >> 7; row < 128; row += 2) {
            int gr = rowBase + row;
            if (gr >= M) break;
            float v = stg[row * 129 + cl];
            if (col < 256) {
                outF[(size_t)gr * 256 + col] = v;
            } else {
                outR[(size_t)gr * 256 + (col - 256)] = relu_f(v + bias[col - 256]);
            }
        }
    } else { // M_READOUT: T[gid] += relu(v + rbi), RLE over sorted gid
        int curg = -1;
        float s = 0.f;
        float bc = bias[col];
        for (int row = t >> 7; row < 128; row += 2) {
            int gr = rowBase + row;
            if (gr >= M) break;
            float v = relu_f(stg[row * 129 + cl] + bc);
            int g = gid[gr];
            if (g != curg) {
                if (curg >= 0) atomicAdd(&outF[(size_t)curg * 256 + col], s);
                curg = g; s = 0.f;
            }
            s += v;
        }
        if (curg >= 0) atomicAdd(&outF[(size_t)curg * 256 + col], s);
    }
}

// ---------------------------------------------------------------------------
// fp32 -> fp16 hi/lo split (activations)
// ---------------------------------------------------------------------------
__global__ __launch_bounds__(256)
void split_k(const float4* __restrict__ in, uint2* __restrict__ H, uint2* __restrict__ L, int n4)
{
    int i = blockIdx.x * blockDim.x + threadIdx.x;
    if (i >= n4) return;
    float4 f = in[i];
    float xs[4] = { f.x, f.y, f.z, f.w };
    union { __half h[4]; uint2 u; } hh, ll;
    #pragma unroll
    for (int j = 0; j < 4; j++) {
        __half hi = __float2half_rn(xs[j]);
        __half lo = __float2half_rn(xs[j] - __half2float(hi));
        hh.h[j] = hi; ll.h[j] = lo;
    }
    H[i] = hh.u; L[i] = ll.u;
}

// All 6 weight transposes in one launch
__global__ __launch_bounds__(256)
void wsplit_all(const float* __restrict__ w0, const float* __restrict__ w1,
                const float* __restrict__ w2, const float* __restrict__ w3,
                const float* __restrict__ w4, const float* __restrict__ w5,
                __half* __restrict__ H)
{
    int idx = blockIdx.x * 256 + threadIdx.x;
    int m = idx >> 16;
    int rem = idx & 65535;
    int n = rem >> 8, k = rem & 255;
    const float* srcs[6] = { w0, w1, w2, w3, w4, w5 };
    H[idx] = __float2half_rn(srcs[m][k * DIM + n]);
}

// ---------------------------------------------------------------------------
// CSR build
// ---------------------------------------------------------------------------
__global__ void zero_i(int* p, int n)
{
    int i = blockIdx.x * blockDim.x + threadIdx.x;
    if (i < n) p[i] = 0;
}
__global__ __launch_bounds__(256)
void hist_k(const int* __restrict__ idxs, int* __restrict__ cnt, int n)
{
    int i = blockIdx.x * blockDim.x + threadIdx.x;
    if (i < n) atomicAdd(&cnt[idxs[i]], 1);
}
__global__ __launch_bounds__(1024)
void scan1_k(const int* __restrict__ deg, int* __restrict__ part, int* __restrict__ bsum)
{
    __shared__ int s[1024];
    int t = threadIdx.x;
    int idx = blockIdx.x * 1024 + t;
    int v = (idx < NN) ? deg[idx] : 0;
    s[t] = v;
    __syncthreads();
    #pragma unroll
    for (int off = 1; off < 1024; off <<= 1) {
        int x = (t >= off) ? s[t - off] : 0;
        __syncthreads();
        s[t] += x;
        __syncthreads();
    }
    if (idx < NN) part[idx] = s[t] - v;
    if (t == 1023) bsum[blockIdx.x] = s[1023];
}
__global__ void scan2_k(int* bsum, int nb)
{
    if (threadIdx.x == 0) {
        int run = 0;
        for (int i = 0; i < nb; i++) { int v = bsum[i]; bsum[i] = run; run += v; }
    }
}
__global__ __launch_bounds__(1024)
void scan3_k(const int* __restrict__ part, const int* __restrict__ bsum,
             int* __restrict__ rowptr, int* __restrict__ woff)
{
    int idx = blockIdx.x * 1024 + threadIdx.x;
    if (idx < NN) {
        int r = part[idx] + bsum[blockIdx.x];
        rowptr[idx] = r;
        woff[idx] = r;
    }
    if (idx == 0) rowptr[NN] = NE;
}
__global__ __launch_bounds__(256)
void fill_k(const int* __restrict__ src, const int* __restrict__ dst,
            int* __restrict__ woff, int* __restrict__ eidsrc, int n)
{
    int e = blockIdx.x * blockDim.x + threadIdx.x;
    if (e >= n) return;
    int pos = atomicAdd(&woff[dst[e]], 1);
    eidsrc[pos] = src[e];
}

// ---------------------------------------------------------------------------
// Fused gather + combine: agg = sum_in hW; h1 = relu(agg+b) + R -> Ch/Cl fp16
// ---------------------------------------------------------------------------
__global__ __launch_bounds__(128)
void gather_combine_k(const float2* __restrict__ hW2, const int* __restrict__ rowptr,
                      const int* __restrict__ eidsrc, const float2* __restrict__ R2,
                      const float* __restrict__ bvec,
                      __half2* __restrict__ H2, __half2* __restrict__ L2)
{
    int n = blockIdx.x;
    int t = threadIdx.x;
    int start = rowptr[n], end = rowptr[n + 1];
    float ax = 0.f, ay = 0.f, bx = 0.f, by = 0.f;
    int j = start;
    for (; j + 1 < end; j += 2) {
        int s0 = __ldg(eidsrc + j);
        int s1 = __ldg(eidsrc + j + 1);
        float2 v0 = hW2[(size_t)s0 * 128 + t];
        float2 v1 = hW2[(size_t)s1 * 128 + t];
        ax += v0.x; ay += v0.y;
        bx += v1.x; by += v1.y;
    }
    if (j < end) {
        int s0 = __ldg(eidsrc + j);
        float2 v0 = hW2[(size_t)s0 * 128 + t];
        ax += v0.x; ay += v0.y;
    }
    ax += bx; ay += by;
    float2 bb = ((const float2*)bvec)[t];
    float2 r = R2[(size_t)n * 128 + t];
    float v0 = relu_f(ax + bb.x) + r.x;
    float v1 = relu_f(ay + bb.y) + r.y;
    __half h0 = __float2half_rn(v0);
    __half h1 = __float2half_rn(v1);
    __half l0 = __float2half_rn(v0 - __half2float(h0));
    __half l1 = __float2half_rn(v1 - __half2float(h1));
    H2[(size_t)n * 128 + t] = __halves2half2(h0, h1);
    L2[(size_t)n * 128 + t] = __halves2half2(l0, l1);
}

__global__ void zero_f4(float4* __restrict__ p, int n4)
{
    int i = blockIdx.x * blockDim.x + threadIdx.x;
    int stride = gridDim.x * blockDim.x;
    float4 z = make_float4(0.f, 0.f, 0.f, 0.f);
    for (; i < n4; i += stride) p[i] = z;
}

// gsum[g,:GF] += T[g,:256] @ Ro[256,GF] + cnt[g]*rbo
__global__ __launch_bounds__(256)
void readout_small(const float* __restrict__ T, const float* __restrict__ Ro,
                   const float* __restrict__ rbo, const int* __restrict__ cnt,
                   float* __restrict__ gsum)
{
    __shared__ float sT[DIM];
    int g = blockIdx.x;
    int t = threadIdx.x;
    sT[t] = T[(size_t)g * DIM + t];
    __syncthreads();
    if (t < GF) {
        float a = 0.f;
        #pragma unroll 8
        for (int k = 0; k < DIM; k++) a += sT[k] * Ro[k * GF + t];
        gsum[(size_t)g * GF + t] += a + (float)cnt[g] * rbo[t];
    }
}

__global__ __launch_bounds__(256)
void predict_k(const float* __restrict__ gsum, const float* __restrict__ Wp,
               const float* __restrict__ bp, float* __restrict__ out)
{
    int warp = (int)((blockIdx.x * (size_t)blockDim.x + threadIdx.x) >> 5);
    int lane = threadIdx.x & 31;
    if (warp >= NG) return;
    const float* row = gsum + (size_t)warp * GF;
    float s = 0.f;
    for (int f = lane; f < GF; f += 32) s += row[f] * Wp[f];
    #pragma unroll
    for (int o = 16; o; o >>= 1) s += __shfl_xor_sync(0xffffffffu, s, o);
    if (lane == 0) out[warp] = s + bp[0];
}

// ---------------------------------------------------------------------------
extern "C" void kernel_launch(void* const* d_in, const int* in_sizes, int n_in,
                              void* d_out, int out_size)
{
    const float* nf[2]  = { (const float*)d_in[0], (const float*)d_in[2] };
    const int*   src[2] = { (const int*)d_in[4],   (const int*)d_in[7] };
    const int*   dst[2] = { (const int*)d_in[5],   (const int*)d_in[8] };
    const int*   gid[2] = { (const int*)d_in[6],   (const int*)d_in[9] };
    const float* W[2]   = { (const float*)d_in[10], (const float*)d_in[14] };
    const float* b[2]   = { (const float*)d_in[11], (const float*)d_in[15] };
    const float* Wr[2]  = { (const float*)d_in[12], (const float*)d_in[16] };
    const float* br[2]  = { (const float*)d_in[13], (const float*)d_in[17] };
    const float* Ri[2]  = { (const float*)d_in[18], (const float*)d_in[22] };
    const float* rbi[2] = { (const float*)d_in[19], (const float*)d_in[23] };
    const float* Ro[2]  = { (const float*)d_in[20], (const float*)d_in[24] };
    const float* rbo[2] = { (const float*)d_in[21], (const float*)d_in[25] };
    const float* Wp = (const float*)d_in[26];
    const float* bp = (const float*)d_in[27];
    float* out = (float*)d_out;

    float *bufA, *bufR, *T, *gsum;
    __half *Ahp, *Alp, *Chp, *Clp, *WtH;
    int *cnt, *deg, *part, *rowptr, *woff, *bsum, *eidsrc;
    cudaGetSymbolAddress((void**)&bufA, g_bufA);
    cudaGetSymbolAddress((void**)&bufR, g_bufR);
    cudaGetSymbolAddress((void**)&Ahp, g_Ah);
    cudaGetSymbolAddress((void**)&Alp, g_Al);
    cudaGetSymbolAddress((void**)&Chp, g_Ch);
    cudaGetSymbolAddress((void**)&Clp, g_Cl);
    cudaGetSymbolAddress((void**)&WtH, g_WtH);
    cudaGetSymbolAddress((void**)&T, g_T);
    cudaGetSymbolAddress((void**)&gsum, g_gsum);
    cudaGetSymbolAddress((void**)&cnt, g_cnt);
    cudaGetSymbolAddress((void**)&deg, g_deg);
    cudaGetSymbolAddress((void**)&part, g_part);
    cudaGetSymbolAddress((void**)&rowptr, g_rowptr);
    cudaGetSymbolAddress((void**)&woff, g_woff);
    cudaGetSymbolAddress((void**)&bsum, g_bsum);
    cudaGetSymbolAddress((void**)&eidsrc, g_eidsrc);

    cudaFuncSetAttribute(gemm_tc<M_DUAL>,    cudaFuncAttributeMaxDynamicSharedMemorySize, GEMM_SMEM);
    cudaFuncSetAttribute(gemm_tc<M_READOUT>, cudaFuncAttributeMaxDynamicSharedMemorySize, GEMM_SMEM);

    const int n4 = NN * DIM / 4;
    const int NB = (NN + 1023) / 1024;
    const dim3 gridDual(4, (NN + 127) / 128);   // BN=128, N=512 ([W;Wr])
    const dim3 gridRo(2, (NN + 127) / 128);     // N=256 (Ri)

    // 1: weight transposes (fp16)
    wsplit_all<<<6 * 65536 / 256, 256>>>(W[0], Wr[0], Ri[0], W[1], Wr[1], Ri[1], WtH);
    // 2: zero gsum
    zero_f4<<<64, 256>>>((float4*)gsum, NG * GF / 4);

    for (int k = 0; k < 2; k++) {
        // 3: split h -> Ah/Al
        split_k<<<(n4 + 255) / 256, 256>>>((const float4*)nf[k], (uint2*)Ahp, (uint2*)Alp, n4);
        // 4: dual GEMM -> bufA (hW), bufR (relu(h@Wr+br))   [ncu-profiled slot]
        gemm_tc<M_DUAL><<<gridDual, 256, GEMM_SMEM>>>(Ahp, Alp,
            WtH + (size_t)(k * 3) * 65536, br[k], nullptr, bufA, bufR, NN);
        // 5-10: CSR build
        zero_i<<<(NN + 255) / 256, 256>>>(deg, NN);
        hist_k<<<(NE + 255) / 256, 256>>>(dst[k], deg, NE);
        scan1_k<<<NB, 1024>>>(deg, part, bsum);
        scan2_k<<<1, 32>>>(bsum, NB);
        scan3_k<<<NB, 1024>>>(part, bsum, rowptr, woff);
        fill_k<<<(NE + 255) / 256, 256>>>(src[k], dst[k], woff, eidsrc, NE);
        // 11: fused gather+combine -> Ch/Cl
        gather_combine_k<<<NN, 128>>>((const float2*)bufA, rowptr, eidsrc,
                                      (const float2*)bufR, b[k],
                                      (__half2*)Chp, (__half2*)Clp);
        // 12-13: T = segment_sum(relu(h1@Ri+rbi))
        zero_f4<<<128, 256>>>((float4*)T, NG * DIM / 4);
        gemm_tc<M_READOUT><<<gridRo, 256, GEMM_SMEM>>>(Chp, Clp,
            WtH + (size_t)(k * 3 + 2) * 65536, rbi[k], gid[k], T, nullptr, NN);
        // 14-16: counts + small readout into gsum
        zero_i<<<2, 256>>>(cnt, NG);
        hist_k<<<(NN + 255) / 256, 256>>>(gid[k], cnt, NN);
        readout_small<<<NG, 256>>>(T, Ro[k], rbo[k], cnt, gsum);
    }

    predict_k<<<(NG * 32 + 255) / 256, 256>>>(gsum, Wp, bp, out);
}

// round 8
// speedup vs baseline: 1.8115x; 1.0213x over previous
#include <cuda_runtime.h>
#include <cuda_fp16.h>
#include <cstdint>

#define NN 50000
#define NE 800000
#define DIM 256
#define GF 200
#define NG 512

// ---------------------------------------------------------------------------
// Scratch (__device__ globals; no allocations allowed)
// ---------------------------------------------------------------------------
__device__ __half g_hW[(size_t)NN * DIM];       // hW (fp16)
__device__ __half g_Rh[(size_t)NN * DIM];       // relu(h@Wr+br) (fp16)
__device__ __half g_Ah[(size_t)NN * DIM];       // h split hi
__device__ __half g_Al[(size_t)NN * DIM];       // h split lo
__device__ __half g_Ch[(size_t)NN * DIM];       // h1 split hi
__device__ __half g_Cl[(size_t)NN * DIM];       // h1 split lo
__device__ __half g_WtH[6 * DIM * DIM];         // transposed weights fp16
__device__ float g_T[NG * DIM];
__device__ float g_gsum[NG * GF];
__device__ int   g_cnt[NG];
// CSR scratch
__device__ int g_deg[NN];
__device__ int g_part[NN];
__device__ int g_rowptr[NN + 1];
__device__ int g_woff[NN];
__device__ int g_bsum[64];
__device__ int g_eidsrc[NE];

enum { M_DUAL = 0, M_READOUT = 1 };

__device__ __forceinline__ float relu_f(float x) { return x > 0.f ? x : 0.f; }

__device__ __forceinline__ uint32_t smem_u32(const void* p) {
    uint32_t a;
    asm("{ .reg .u64 t; cvta.to.shared.u64 t, %1; cvt.u32.u64 %0, t; }" : "=r"(a) : "l"(p));
    return a;
}
__device__ __forceinline__ uint32_t swz(uint32_t off) { return off ^ ((off >> 3) & 0x70); }
__device__ __forceinline__ void cpa16(uint32_t s, const void* g, int sz) {
    asm volatile("cp.async.cg.shared.global [%0], [%1], 16, %2;" :: "r"(s), "l"(g), "r"(sz) : "memory");
}
__device__ __forceinline__ void ldsm4(uint32_t* r, uint32_t addr) {
    asm volatile("ldmatrix.sync.aligned.m8n8.x4.shared.b16 {%0,%1,%2,%3}, [%4];"
        : "=r"(r[0]), "=r"(r[1]), "=r"(r[2]), "=r"(r[3]) : "r"(addr));
}
__device__ __forceinline__ void mma16816(float* c, const uint32_t* a, const uint32_t* b) {
    asm volatile("mma.sync.aligned.m16n8k16.row.col.f32.f16.f16.f32 "
        "{%0,%1,%2,%3}, {%4,%5,%6,%7}, {%8,%9}, {%0,%1,%2,%3};"
        : "+f"(c[0]), "+f"(c[1]), "+f"(c[2]), "+f"(c[3])
        : "r"(a[0]), "r"(a[1]), "r"(a[2]), "r"(a[3]), "r"(b[0]), "r"(b[1]));
}

// ---------------------------------------------------------------------------
// HMMA GEMM: BM=128, BN=128, BK=64. 256 threads = 8 warps, warp tile 32x64.
// fp16x2: D = Ah*Bh + Al*Bh (fp32 accum). A/B smem double-buffered; B frags
// software-pipelined in registers. 2 CTAs/SM (96KB smem, 128 regs).
// ---------------------------------------------------------------------------
static const int SM_A = 0;                 // 2buf x 2split x 16KB = 64KB
static const int SM_B = 65536;             // 2buf x 16KB = 32KB
static const int GEMM_SMEM = 98304;        // 96KB

template <int MODE>
__global__ __launch_bounds__(256, 2)
void gemm_tc(const __half* __restrict__ Ah, const __half* __restrict__ Al,
             const __half* __restrict__ Bh,
             const float* __restrict__ bias,   // DUAL: br ; READOUT: rbi
             const int* __restrict__ gid,      // READOUT
             float* __restrict__ outF,         // READOUT: T
             __half* __restrict__ outH,        // DUAL: hW (cols 0..255)
             __half* __restrict__ outRh,       // DUAL: R  (cols 256..511)
             int M)
{
    extern __shared__ char smem_raw[];
    uint32_t sb = smem_u32(smem_raw);
    const int t = threadIdx.x;
    const int lane = t & 31;
    const int wid = t >> 5;
    const int rowBase = blockIdx.y * 128;
    const int colBase = blockIdx.x * 128;

    const int m0 = (wid & 3) * 32;        // warp m origin (4 m-groups)
    const int n0 = (wid >> 2) * 64;       // warp n origin (2 n-groups)

    const int ar = (lane & 7) + ((lane >> 3) & 1) * 8;
    const int ak = ((lane >> 4) & 1) * 8;
    const int br_ = (lane & 7) + ((lane >> 4) & 1) * 8;
    const int bk = ((lane >> 3) & 1) * 8;

    // loop-invariant swizzled bases (kk folds in via XOR)
    uint32_t aRel[2], bRel[4];
    #pragma unroll
    for (int mt = 0; mt < 2; mt++)
        aRel[mt] = swz((uint32_t)(m0 + mt * 16 + ar) * 128 + ak * 2);
    #pragma unroll
    for (int q = 0; q < 4; q++)
        bRel[q] = swz((uint32_t)(n0 + q * 16 + br_) * 128 + bk * 2);

    const __half* Asrc[2] = { Ah, Al };
    auto loadAB = [&](int c, int buf) {
        #pragma unroll
        for (int i = 0; i < 8; i++) {
            int idx = i * 256 + t;
            int split = idx >> 10;
            int w = idx & 1023;
            int row = w >> 3, seg = w & 7;
            int gr = rowBase + row;
            int ok = gr < M;
            uint32_t sa = sb + SM_A + buf * 32768 + split * 16384 + swz(row * 128 + seg * 16);
            const __half* gp = Asrc[split] + (size_t)(ok ? gr : 0) * 256 + c * 64 + seg * 8;
            cpa16(sa, gp, ok ? 16 : 0);
        }
        #pragma unroll
        for (int i = 0; i < 4; i++) {
            int idx = i * 256 + t;
            int row = idx >> 3, seg = idx & 7;
            uint32_t sa = sb + SM_B + buf * 16384 + swz(row * 128 + seg * 16);
            const __half* gp = Bh + (size_t)(colBase + row) * 256 + c * 64 + seg * 8;
            cpa16(sa, gp, 16);
        }
    };
    loadAB(0, 0);
    asm volatile("cp.async.commit_group;" ::: "memory");

    float acc[2][8][4] = {};

    #pragma unroll
    for (int c = 0; c < 4; c++) {
        if (c < 3) {
            loadAB(c + 1, (c + 1) & 1);
            asm volatile("cp.async.commit_group;" ::: "memory");
            asm volatile("cp.async.wait_group 1;" ::: "memory");
        } else {
            asm volatile("cp.async.wait_group 0;" ::: "memory");
        }
        __syncthreads();

        uint32_t aH = sb + SM_A + (c & 1) * 32768;
        uint32_t aL = aH + 16384;
        uint32_t bB = sb + SM_B + (c & 1) * 16384;

        // B-fragment software pipeline: load kk=0 set, prefetch next inside loop
        uint32_t bhbuf[2][4][4];
        #pragma unroll
        for (int q = 0; q < 4; q++)
            ldsm4(bhbuf[0][q], bB + bRel[q]);

        #pragma unroll
        for (int kk2 = 0; kk2 < 128; kk2 += 32) {   // kk*2 byte offset
            const int cur = (kk2 >> 5) & 1, nxt = cur ^ 1;
            uint32_t ah[2][4], al[2][4];
            #pragma unroll
            for (int mt = 0; mt < 2; mt++)
                ldsm4(ah[mt], aH + (aRel[mt] ^ kk2));
            if (kk2 < 96) {
                #pragma unroll
                for (int q = 0; q < 4; q++)
                    ldsm4(bhbuf[nxt][q], bB + (bRel[q] ^ (kk2 + 32)));
            }
            #pragma unroll
            for (int mt = 0; mt < 2; mt++)
                ldsm4(al[mt], aL + (aRel[mt] ^ kk2));
            // hi term over all 16 accs
            #pragma unroll
            for (int mt = 0; mt < 2; mt++)
                #pragma unroll
                for (int nt = 0; nt < 8; nt++)
                    mma16816(acc[mt][nt], ah[mt], &bhbuf[cur][nt >> 1][(nt & 1) * 2]);
            // lo term
            #pragma unroll
            for (int mt = 0; mt < 2; mt++)
                #pragma unroll
                for (int nt = 0; nt < 8; nt++)
                    mma16816(acc[mt][nt], al[mt], &bhbuf[cur][nt >> 1][(nt & 1) * 2]);
        }
        __syncthreads();
    }

    // ---- epilogue: regs -> SMEM staging (128 x 128, stride 129) ----
    float* stg = (float*)smem_raw;
    #pragma unroll
    for (int mt = 0; mt < 2; mt++) {
        #pragma unroll
        for (int nt = 0; nt < 8; nt++) {
            int r = m0 + mt * 16 + (lane >> 2);
            int cc = n0 + nt * 8 + (lane & 3) * 2;
            stg[r * 129 + cc]           = acc[mt][nt][0];
            stg[r * 129 + cc + 1]       = acc[mt][nt][1];
            stg[(r + 8) * 129 + cc]     = acc[mt][nt][2];
            stg[(r + 8) * 129 + cc + 1] = acc[mt][nt][3];
        }
    }
    __syncthreads();

    const int cl = t & 127;
    const int col = colBase + cl;
    if (MODE == M_DUAL) {
        for (int row = t >> 7; row < 128; row += 2) {
            int gr = rowBase + row;
            if (gr >= M) break;
            float v = stg[row * 129 + cl];
            if (col < 256) {
                outH[(size_t)gr * 256 + col] = __float2half_rn(v);
            } else {
                outRh[(size_t)gr * 256 + (col - 256)] = __float2half_rn(relu_f(v + bias[col - 256]));
            }
        }
    } else { // M_READOUT: T[gid] += relu(v + rbi), RLE over sorted gid
        int curg = -1;
        float s = 0.f;
        float bc = bias[col];
        for (int row = t >> 7; row < 128; row += 2) {
            int gr = rowBase + row;
            if (gr >= M) break;
            float v = relu_f(stg[row * 129 + cl] + bc);
            int g = gid[gr];
            if (g != curg) {
                if (curg >= 0) atomicAdd(&outF[(size_t)curg * 256 + col], s);
                curg = g; s = 0.f;
            }
            s += v;
        }
        if (curg >= 0) atomicAdd(&outF[(size_t)curg * 256 + col], s);
    }
}

// ---------------------------------------------------------------------------
// fp32 -> fp16 hi/lo split (activations)
// ---------------------------------------------------------------------------
__global__ __launch_bounds__(256)
void split_k(const float4* __restrict__ in, uint2* __restrict__ H, uint2* __restrict__ L, int n4)
{
    int i = blockIdx.x * blockDim.x + threadIdx.x;
    if (i >= n4) return;
    float4 f = in[i];
    float xs[4] = { f.x, f.y, f.z, f.w };
    union { __half h[4]; uint2 u; } hh, ll;
    #pragma unroll
    for (int j = 0; j < 4; j++) {
        __half hi = __float2half_rn(xs[j]);
        __half lo = __float2half_rn(xs[j] - __half2float(hi));
        hh.h[j] = hi; ll.h[j] = lo;
    }
    H[i] = hh.u; L[i] = ll.u;
}

// All 6 weight transposes in one launch
__global__ __launch_bounds__(256)
void wsplit_all(const float* __restrict__ w0, const float* __restrict__ w1,
                const float* __restrict__ w2, const float* __restrict__ w3,
                const float* __restrict__ w4, const float* __restrict__ w5,
                __half* __restrict__ H)
{
    int idx = blockIdx.x * 256 + threadIdx.x;
    int m = idx >> 16;
    int rem = idx & 65535;
    int n = rem >> 8, k = rem & 255;
    const float* srcs[6] = { w0, w1, w2, w3, w4, w5 };
    H[idx] = __float2half_rn(srcs[m][k * DIM + n]);
}

// ---------------------------------------------------------------------------
// CSR build
// ---------------------------------------------------------------------------
__global__ void zero_i(int* p, int n)
{
    int i = blockIdx.x * blockDim.x + threadIdx.x;
    if (i < n) p[i] = 0;
}
__global__ __launch_bounds__(256)
void hist_k(const int* __restrict__ idxs, int* __restrict__ cnt, int n)
{
    int i = blockIdx.x * blockDim.x + threadIdx.x;
    if (i < n) atomicAdd(&cnt[idxs[i]], 1);
}
__global__ __launch_bounds__(1024)
void scan1_k(const int* __restrict__ deg, int* __restrict__ part, int* __restrict__ bsum)
{
    __shared__ int s[1024];
    int t = threadIdx.x;
    int idx = blockIdx.x * 1024 + t;
    int v = (idx < NN) ? deg[idx] : 0;
    s[t] = v;
    __syncthreads();
    #pragma unroll
    for (int off = 1; off < 1024; off <<= 1) {
        int x = (t >= off) ? s[t - off] : 0;
        __syncthreads();
        s[t] += x;
        __syncthreads();
    }
    if (idx < NN) part[idx] = s[t] - v;
    if (t == 1023) bsum[blockIdx.x] = s[1023];
}
__global__ void scan2_k(int* bsum, int nb)
{
    if (threadIdx.x == 0) {
        int run = 0;
        for (int i = 0; i < nb; i++) { int v = bsum[i]; bsum[i] = run; run += v; }
    }
}
__global__ __launch_bounds__(1024)
void scan3_k(const int* __restrict__ part, const int* __restrict__ bsum,
             int* __restrict__ rowptr, int* __restrict__ woff)
{
    int idx = blockIdx.x * 1024 + threadIdx.x;
    if (idx < NN) {
        int r = part[idx] + bsum[blockIdx.x];
        rowptr[idx] = r;
        woff[idx] = r;
    }
    if (idx == 0) rowptr[NN] = NE;
}
__global__ __launch_bounds__(256)
void fill_k(const int* __restrict__ src, const int* __restrict__ dst,
            int* __restrict__ woff, int* __restrict__ eidsrc, int n)
{
    int e = blockIdx.x * blockDim.x + threadIdx.x;
    if (e >= n) return;
    int pos = atomicAdd(&woff[dst[e]], 1);
    eidsrc[pos] = src[e];
}

// ---------------------------------------------------------------------------
// Fused gather + combine (fp16 hW): agg = sum_in hW; h1 = relu(agg+b) + R
// -> Ch/Cl fp16. 128 threads/node, thread t owns cols {2t, 2t+1}.
// ---------------------------------------------------------------------------
__global__ __launch_bounds__(128)
void gather_combine_k(const __half2* __restrict__ hW2, const int* __restrict__ rowptr,
                      const int* __restrict__ eidsrc, const __half2* __restrict__ R2,
                      const float* __restrict__ bvec,
                      __half2* __restrict__ H2, __half2* __restrict__ L2)
{
    int n = blockIdx.x;
    int t = threadIdx.x;
    int start = rowptr[n], end = rowptr[n + 1];
    float ax = 0.f, ay = 0.f, bx = 0.f, by = 0.f;
    int j = start;
    for (; j + 1 < end; j += 2) {
        int s0 = __ldg(eidsrc + j);
        int s1 = __ldg(eidsrc + j + 1);
        float2 v0 = __half22float2(hW2[(size_t)s0 * 128 + t]);
        float2 v1 = __half22float2(hW2[(size_t)s1 * 128 + t]);
        ax += v0.x; ay += v0.y;
        bx += v1.x; by += v1.y;
    }
    if (j < end) {
        int s0 = __ldg(eidsrc + j);
        float2 v0 = __half22float2(hW2[(size_t)s0 * 128 + t]);
        ax += v0.x; ay += v0.y;
    }
    ax += bx; ay += by;
    float2 bb = ((const float2*)bvec)[t];
    float2 r = __half22float2(R2[(size_t)n * 128 + t]);
    float v0 = relu_f(ax + bb.x) + r.x;
    float v1 = relu_f(ay + bb.y) + r.y;
    __half h0 = __float2half_rn(v0);
    __half h1 = __float2half_rn(v1);
    __half l0 = __float2half_rn(v0 - __half2float(h0));
    __half l1 = __float2half_rn(v1 - __half2float(h1));
    H2[(size_t)n * 128 + t] = __halves2half2(h0, h1);
    L2[(size_t)n * 128 + t] = __halves2half2(l0, l1);
}

__global__ void zero_f4(float4* __restrict__ p, int n4)
{
    int i = blockIdx.x * blockDim.x + threadIdx.x;
    int stride = gridDim.x * blockDim.x;
    float4 z = make_float4(0.f, 0.f, 0.f, 0.f);
    for (; i < n4; i += stride) p[i] = z;
}

// gsum[g,:GF] += T[g,:256] @ Ro[256,GF] + cnt[g]*rbo
__global__ __launch_bounds__(256)
void readout_small(const float* __restrict__ T, const float* __restrict__ Ro,
                   const float* __restrict__ rbo, const int* __restrict__ cnt,
                   float* __restrict__ gsum)
{
    __shared__ float sT[DIM];
    int g = blockIdx.x;
    int t = threadIdx.x;
    sT[t] = T[(size_t)g * DIM + t];
    __syncthreads();
    if (t < GF) {
        float a = 0.f;
        #pragma unroll 8
        for (int k = 0; k < DIM; k++) a += sT[k] * Ro[k * GF + t];
        gsum[(size_t)g * GF + t] += a + (float)cnt[g] * rbo[t];
    }
}

__global__ __launch_bounds__(256)
void predict_k(const float* __restrict__ gsum, const float* __restrict__ Wp,
               const float* __restrict__ bp, float* __restrict__ out)
{
    int warp = (int)((blockIdx.x * (size_t)blockDim.x + threadIdx.x) >> 5);
    int lane = threadIdx.x & 31;
    if (warp >= NG) return;
    const float* row = gsum + (size_t)warp * GF;
    float s = 0.f;
    for (int f = lane; f < GF; f += 32) s += row[f] * Wp[f];
    #pragma unroll
    for (int o = 16; o; o >>= 1) s += __shfl_xor_sync(0xffffffffu, s, o);
    if (lane == 0) out[warp] = s + bp[0];
}

// ---------------------------------------------------------------------------
extern "C" void kernel_launch(void* const* d_in, const int* in_sizes, int n_in,
                              void* d_out, int out_size)
{
    const float* nf[2]  = { (const float*)d_in[0], (const float*)d_in[2] };
    const int*   src[2] = { (const int*)d_in[4],   (const int*)d_in[7] };
    const int*   dst[2] = { (const int*)d_in[5],   (const int*)d_in[8] };
    const int*   gid[2] = { (const int*)d_in[6],   (const int*)d_in[9] };
    const float* W[2]   = { (const float*)d_in[10], (const float*)d_in[14] };
    const float* b[2]   = { (const float*)d_in[11], (const float*)d_in[15] };
    const float* Wr[2]  = { (const float*)d_in[12], (const float*)d_in[16] };
    const float* br[2]  = { (const float*)d_in[13], (const float*)d_in[17] };
    const float* Ri[2]  = { (const float*)d_in[18], (const float*)d_in[22] };
    const float* rbi[2] = { (const float*)d_in[19], (const float*)d_in[23] };
    const float* Ro[2]  = { (const float*)d_in[20], (const float*)d_in[24] };
    const float* rbo[2] = { (const float*)d_in[21], (const float*)d_in[25] };
    const float* Wp = (const float*)d_in[26];
    const float* bp = (const float*)d_in[27];
    float* out = (float*)d_out;

    float *T, *gsum;
    __half *hWp, *Rhp, *Ahp, *Alp, *Chp, *Clp, *WtH;
    int *cnt, *deg, *part, *rowptr, *woff, *bsum, *eidsrc;
    cudaGetSymbolAddress((void**)&hWp, g_hW);
    cudaGetSymbolAddress((void**)&Rhp, g_Rh);
    cudaGetSymbolAddress((void**)&Ahp, g_Ah);
    cudaGetSymbolAddress((void**)&Alp, g_Al);
    cudaGetSymbolAddress((void**)&Chp, g_Ch);
    cudaGetSymbolAddress((void**)&Clp, g_Cl);
    cudaGetSymbolAddress((void**)&WtH, g_WtH);
    cudaGetSymbolAddress((void**)&T, g_T);
    cudaGetSymbolAddress((void**)&gsum, g_gsum);
    cudaGetSymbolAddress((void**)&cnt, g_cnt);
    cudaGetSymbolAddress((void**)&deg, g_deg);
    cudaGetSymbolAddress((void**)&part, g_part);
    cudaGetSymbolAddress((void**)&rowptr, g_rowptr);
    cudaGetSymbolAddress((void**)&woff, g_woff);
    cudaGetSymbolAddress((void**)&bsum, g_bsum);
    cudaGetSymbolAddress((void**)&eidsrc, g_eidsrc);

    cudaFuncSetAttribute(gemm_tc<M_DUAL>,    cudaFuncAttributeMaxDynamicSharedMemorySize, GEMM_SMEM);
    cudaFuncSetAttribute(gemm_tc<M_READOUT>, cudaFuncAttributeMaxDynamicSharedMemorySize, GEMM_SMEM);

    const int n4 = NN * DIM / 4;
    const int NB = (NN + 1023) / 1024;
    const dim3 gridDual(4, (NN + 127) / 128);   // BN=128, N=512 ([W;Wr])
    const dim3 gridRo(2, (NN + 127) / 128);     // N=256 (Ri)

    // 1: weight transposes (fp16)
    wsplit_all<<<6 * 65536 / 256, 256>>>(W[0], Wr[0], Ri[0], W[1], Wr[1], Ri[1], WtH);
    // 2: zero gsum
    zero_f4<<<64, 256>>>((float4*)gsum, NG * GF / 4);

    for (int k = 0; k < 2; k++) {
        // 3: split h -> Ah/Al
        split_k<<<(n4 + 255) / 256, 256>>>((const float4*)nf[k], (uint2*)Ahp, (uint2*)Alp, n4);
        // 4: dual GEMM -> hW (fp16), R (fp16)   [ncu-profiled slot]
        gemm_tc<M_DUAL><<<gridDual, 256, GEMM_SMEM>>>(Ahp, Alp,
            WtH + (size_t)(k * 3) * 65536, br[k], nullptr, nullptr, hWp, Rhp, NN);
        // 5-10: CSR build
        zero_i<<<(NN + 255) / 256, 256>>>(deg, NN);
        hist_k<<<(NE + 255) / 256, 256>>>(dst[k], deg, NE);
        scan1_k<<<NB, 1024>>>(deg, part, bsum);
        scan2_k<<<1, 32>>>(bsum, NB);
        scan3_k<<<NB, 1024>>>(part, bsum, rowptr, woff);
        fill_k<<<(NE + 255) / 256, 256>>>(src[k], dst[k], woff, eidsrc, NE);
        // 11: fused gather+combine -> Ch/Cl
        gather_combine_k<<<NN, 128>>>((const __half2*)hWp, rowptr, eidsrc,
                                      (const __half2*)Rhp, b[k],
                                      (__half2*)Chp, (__half2*)Clp);
        // 12-13: T = segment_sum(relu(h1@Ri+rbi))
        zero_f4<<<128, 256>>>((float4*)T, NG * DIM / 4);
        gemm_tc<M_READOUT><<<gridRo, 256, GEMM_SMEM>>>(Chp, Clp,
            WtH + (size_t)(k * 3 + 2) * 65536, rbi[k], gid[k], T, nullptr, nullptr, NN);
        // 14-16: counts + small readout into gsum
        zero_i<<<2, 256>>>(cnt, NG);
        hist_k<<<(NN + 255) / 256, 256>>>(gid[k], cnt, NN);
        readout_small<<<NG, 256>>>(T, Ro[k], rbo[k], cnt, gsum);
    }

    predict_k<<<(NG * 32 + 255) / 256, 256>>>(gsum, Wp, bp, out);
}

// round 9
// speedup vs baseline: 2.0570x; 1.1355x over previous
#include <cuda_runtime.h>
#include <cuda_fp16.h>
#include <cstdint>

#define NN 50000
#define NE 800000
#define DIM 256
#define GF 200
#define NG 512

// ---------------------------------------------------------------------------
// Scratch (__device__ globals; no allocations allowed)
// ---------------------------------------------------------------------------
__device__ __half g_hW[(size_t)NN * DIM];       // hW (fp16)
__device__ __half g_Rh[(size_t)NN * DIM];       // relu(h@Wr+br) (fp16)
__device__ __half g_Ah[(size_t)NN * DIM];       // h split hi
__device__ __half g_Al[(size_t)NN * DIM];       // h split lo
__device__ __half g_Ch[(size_t)NN * DIM];       // h1 (fp16, single)
__device__ __half g_WtH[6 * DIM * DIM];         // transposed weights fp16
__device__ float g_T[NG * DIM];
__device__ float g_gsum[NG * GF];
__device__ int   g_cnt[NG];
// CSR scratch
__device__ int g_deg[NN];
__device__ int g_part[NN];
__device__ int g_rowptr[NN + 1];
__device__ int g_woff[NN];
__device__ int g_bsum[64];
__device__ int g_eidsrc[NE];

enum { M_DUAL = 0, M_READOUT = 1 };

__device__ __forceinline__ float relu_f(float x) { return x > 0.f ? x : 0.f; }

__device__ __forceinline__ uint32_t smem_u32(const void* p) {
    uint32_t a;
    asm("{ .reg .u64 t; cvta.to.shared.u64 t, %1; cvt.u32.u64 %0, t; }" : "=r"(a) : "l"(p));
    return a;
}
__device__ __forceinline__ uint32_t swz(uint32_t off) { return off ^ ((off >> 3) & 0x70); }
__device__ __forceinline__ void cpa16(uint32_t s, const void* g, int sz) {
    asm volatile("cp.async.cg.shared.global [%0], [%1], 16, %2;" :: "r"(s), "l"(g), "r"(sz) : "memory");
}
__device__ __forceinline__ void ldsm4(uint32_t* r, uint32_t addr) {
    asm volatile("ldmatrix.sync.aligned.m8n8.x4.shared.b16 {%0,%1,%2,%3}, [%4];"
        : "=r"(r[0]), "=r"(r[1]), "=r"(r[2]), "=r"(r[3]) : "r"(addr));
}
__device__ __forceinline__ void mma16816(float* c, const uint32_t* a, const uint32_t* b) {
    asm volatile("mma.sync.aligned.m16n8k16.row.col.f32.f16.f16.f32 "
        "{%0,%1,%2,%3}, {%4,%5,%6,%7}, {%8,%9}, {%0,%1,%2,%3};"
        : "+f"(c[0]), "+f"(c[1]), "+f"(c[2]), "+f"(c[3])
        : "r"(a[0]), "r"(a[1]), "r"(a[2]), "r"(a[3]), "r"(b[0]), "r"(b[1]));
}

// ---------------------------------------------------------------------------
// HMMA GEMM: BM=128, BN=128, BK=64. 256 threads = 8 warps, warp tile 32x64.
// D = Ah*Bh (+ Al*Bh where useLo). DUAL: lo only for colBase<256 (the W half).
// READOUT: 1-term. A/B smem double-buffered. 2 CTAs/SM (96KB smem, 128 regs).
// ---------------------------------------------------------------------------
static const int SM_A = 0;                 // 2buf x 2split x 16KB = 64KB
static const int SM_B = 65536;             // 2buf x 16KB = 32KB
static const int GEMM_SMEM = 98304;        // 96KB

template <int MODE>
__global__ __launch_bounds__(256, 2)
void gemm_tc(const __half* __restrict__ Ah, const __half* __restrict__ Al,
             const __half* __restrict__ Bh,
             const float* __restrict__ bias,   // DUAL: br ; READOUT: rbi
             const int* __restrict__ gid,      // READOUT
             float* __restrict__ outF,         // READOUT: T
             __half* __restrict__ outH,        // DUAL: hW (cols 0..255)
             __half* __restrict__ outRh,       // DUAL: R  (cols 256..511)
             int M)
{
    extern __shared__ char smem_raw[];
    uint32_t sb = smem_u32(smem_raw);
    const int t = threadIdx.x;
    const int lane = t & 31;
    const int wid = t >> 5;
    const int rowBase = blockIdx.y * 128;
    const int colBase = blockIdx.x * 128;
    const bool useLo = (MODE == M_DUAL) && (colBase < 256);

    const int m0 = (wid & 3) * 32;        // warp m origin (4 m-groups)
    const int n0 = (wid >> 2) * 64;       // warp n origin (2 n-groups)

    const int ar = (lane & 7) + ((lane >> 3) & 1) * 8;
    const int ak = ((lane >> 4) & 1) * 8;
    const int br_ = (lane & 7) + ((lane >> 4) & 1) * 8;
    const int bk = ((lane >> 3) & 1) * 8;

    // loop-invariant swizzled bases (kk folds in via XOR)
    uint32_t aRel[2], bRel[4];
    #pragma unroll
    for (int mt = 0; mt < 2; mt++)
        aRel[mt] = swz((uint32_t)(m0 + mt * 16 + ar) * 128 + ak * 2);
    #pragma unroll
    for (int q = 0; q < 4; q++)
        bRel[q] = swz((uint32_t)(n0 + q * 16 + br_) * 128 + bk * 2);

    const __half* Asrc[2] = { Ah, Al };
    const int nAiter = useLo ? 8 : 4;
    auto loadAB = [&](int c, int buf) {
        for (int i = 0; i < nAiter; i++) {       // A: splits x 1024 16B units
            int idx = i * 256 + t;
            int split = idx >> 10;
            int w = idx & 1023;
            int row = w >> 3, seg = w & 7;
            int gr = rowBase + row;
            int ok = gr < M;
            uint32_t sa = sb + SM_A + buf * 32768 + split * 16384 + swz(row * 128 + seg * 16);
            const __half* gp = Asrc[split] + (size_t)(ok ? gr : 0) * 256 + c * 64 + seg * 8;
            cpa16(sa, gp, ok ? 16 : 0);
        }
        #pragma unroll
        for (int i = 0; i < 4; i++) {            // B: 1024 16B units
            int idx = i * 256 + t;
            int row = idx >> 3, seg = idx & 7;
            uint32_t sa = sb + SM_B + buf * 16384 + swz(row * 128 + seg * 16);
            const __half* gp = Bh + (size_t)(colBase + row) * 256 + c * 64 + seg * 8;
            cpa16(sa, gp, 16);
        }
    };
    loadAB(0, 0);
    asm volatile("cp.async.commit_group;" ::: "memory");

    float acc[2][8][4] = {};

    #pragma unroll
    for (int c = 0; c < 4; c++) {
        if (c < 3) {
            loadAB(c + 1, (c + 1) & 1);
            asm volatile("cp.async.commit_group;" ::: "memory");
            asm volatile("cp.async.wait_group 1;" ::: "memory");
        } else {
            asm volatile("cp.async.wait_group 0;" ::: "memory");
        }
        __syncthreads();

        uint32_t aH = sb + SM_A + (c & 1) * 32768;
        uint32_t aL = aH + 16384;
        uint32_t bB = sb + SM_B + (c & 1) * 16384;

        #pragma unroll
        for (int kk2 = 0; kk2 < 128; kk2 += 32) {   // kk*2 byte offset
            uint32_t ah[2][4], al[2][4], bh[4][4];
            #pragma unroll
            for (int mt = 0; mt < 2; mt++)
                ldsm4(ah[mt], aH + (aRel[mt] ^ kk2));
            #pragma unroll
            for (int q = 0; q < 4; q++)
                ldsm4(bh[q], bB + (bRel[q] ^ kk2));
            if (useLo) {
                #pragma unroll
                for (int mt = 0; mt < 2; mt++)
                    ldsm4(al[mt], aL + (aRel[mt] ^ kk2));
            }
            // hi term over all 16 accs
            #pragma unroll
            for (int mt = 0; mt < 2; mt++)
                #pragma unroll
                for (int nt = 0; nt < 8; nt++)
                    mma16816(acc[mt][nt], ah[mt], &bh[nt >> 1][(nt & 1) * 2]);
            if (useLo) {
                #pragma unroll
                for (int mt = 0; mt < 2; mt++)
                    #pragma unroll
                    for (int nt = 0; nt < 8; nt++)
                        mma16816(acc[mt][nt], al[mt], &bh[nt >> 1][(nt & 1) * 2]);
            }
        }
        __syncthreads();
    }

    if (MODE == M_DUAL) {
        // ---- fp16 staging (128 x 128, stride 136 halves: conflict-free) ----
        __half* stg = (__half*)smem_raw;
        #pragma unroll
        for (int mt = 0; mt < 2; mt++) {
            #pragma unroll
            for (int nt = 0; nt < 8; nt++) {
                int r = m0 + mt * 16 + (lane >> 2);
                int cc = n0 + nt * 8 + (lane & 3) * 2;
                *(__half2*)&stg[r * 136 + cc] =
                    __floats2half2_rn(acc[mt][nt][0], acc[mt][nt][1]);
                *(__half2*)&stg[(r + 8) * 136 + cc] =
                    __floats2half2_rn(acc[mt][nt][2], acc[mt][nt][3]);
            }
        }
        __syncthreads();
        const int cl = t & 127;
        const int col = colBase + cl;
        for (int row = t >> 7; row < 128; row += 2) {
            int gr = rowBase + row;
            if (gr >= M) break;
            __half v = stg[row * 136 + cl];
            if (col < 256) {
                outH[(size_t)gr * 256 + col] = v;
            } else {
                float f = relu_f(__half2float(v) + bias[col - 256]);
                outRh[(size_t)gr * 256 + (col - 256)] = __float2half_rn(f);
            }
        }
    } else {
        // ---- f32 staging + RLE atomics into T ----
        float* stg = (float*)smem_raw;
        #pragma unroll
        for (int mt = 0; mt < 2; mt++) {
            #pragma unroll
            for (int nt = 0; nt < 8; nt++) {
                int r = m0 + mt * 16 + (lane >> 2);
                int cc = n0 + nt * 8 + (lane & 3) * 2;
                stg[r * 129 + cc]           = acc[mt][nt][0];
                stg[r * 129 + cc + 1]       = acc[mt][nt][1];
                stg[(r + 8) * 129 + cc]     = acc[mt][nt][2];
                stg[(r + 8) * 129 + cc + 1] = acc[mt][nt][3];
            }
        }
        __syncthreads();
        const int cl = t & 127;
        const int col = colBase + cl;
        int curg = -1;
        float s = 0.f;
        float bc = bias[col];
        for (int row = t >> 7; row < 128; row += 2) {
            int gr = rowBase + row;
            if (gr >= M) break;
            float v = relu_f(stg[row * 129 + cl] + bc);
            int g = gid[gr];
            if (g != curg) {
                if (curg >= 0) atomicAdd(&outF[(size_t)curg * 256 + col], s);
                curg = g; s = 0.f;
            }
            s += v;
        }
        if (curg >= 0) atomicAdd(&outF[(size_t)curg * 256 + col], s);
    }
}

// ---------------------------------------------------------------------------
// fp32 -> fp16 hi/lo split (activations)
// ---------------------------------------------------------------------------
__global__ __launch_bounds__(256)
void split_k(const float4* __restrict__ in, uint2* __restrict__ H, uint2* __restrict__ L, int n4)
{
    int i = blockIdx.x * blockDim.x + threadIdx.x;
    if (i >= n4) return;
    float4 f = in[i];
    float xs[4] = { f.x, f.y, f.z, f.w };
    union { __half h[4]; uint2 u; } hh, ll;
    #pragma unroll
    for (int j = 0; j < 4; j++) {
        __half hi = __float2half_rn(xs[j]);
        __half lo = __float2half_rn(xs[j] - __half2float(hi));
        hh.h[j] = hi; ll.h[j] = lo;
    }
    H[i] = hh.u; L[i] = ll.u;
}

// All 6 weight transposes in one launch
__global__ __launch_bounds__(256)
void wsplit_all(const float* __restrict__ w0, const float* __restrict__ w1,
                const float* __restrict__ w2, const float* __restrict__ w3,
                const float* __restrict__ w4, const float* __restrict__ w5,
                __half* __restrict__ H)
{
    int idx = blockIdx.x * 256 + threadIdx.x;
    int m = idx >> 16;
    int rem = idx & 65535;
    int n = rem >> 8, k = rem & 255;
    const float* srcs[6] = { w0, w1, w2, w3, w4, w5 };
    H[idx] = __float2half_rn(srcs[m][k * DIM + n]);
}

// ---------------------------------------------------------------------------
// CSR build
// ---------------------------------------------------------------------------
__global__ void zero_i(int* p, int n)
{
    int i = blockIdx.x * blockDim.x + threadIdx.x;
    if (i < n) p[i] = 0;
}
__global__ __launch_bounds__(256)
void hist_k(const int* __restrict__ idxs, int* __restrict__ cnt, int n)
{
    int i = blockIdx.x * blockDim.x + threadIdx.x;
    if (i < n) atomicAdd(&cnt[idxs[i]], 1);
}
__global__ __launch_bounds__(1024)
void scan1_k(const int* __restrict__ deg, int* __restrict__ part, int* __restrict__ bsum)
{
    __shared__ int s[1024];
    int t = threadIdx.x;
    int idx = blockIdx.x * 1024 + t;
    int v = (idx < NN) ? deg[idx] : 0;
    s[t] = v;
    __syncthreads();
    #pragma unroll
    for (int off = 1; off < 1024; off <<= 1) {
        int x = (t >= off) ? s[t - off] : 0;
        __syncthreads();
        s[t] += x;
        __syncthreads();
    }
    if (idx < NN) part[idx] = s[t] - v;
    if (t == 1023) bsum[blockIdx.x] = s[1023];
}
__global__ void scan2_k(int* bsum, int nb)
{
    if (threadIdx.x == 0) {
        int run = 0;
        for (int i = 0; i < nb; i++) { int v = bsum[i]; bsum[i] = run; run += v; }
    }
}
__global__ __launch_bounds__(1024)
void scan3_k(const int* __restrict__ part, const int* __restrict__ bsum,
             int* __restrict__ rowptr, int* __restrict__ woff)
{
    int idx = blockIdx.x * 1024 + threadIdx.x;
    if (idx < NN) {
        int r = part[idx] + bsum[blockIdx.x];
        rowptr[idx] = r;
        woff[idx] = r;
    }
    if (idx == 0) rowptr[NN] = NE;
}
__global__ __launch_bounds__(256)
void fill_k(const int* __restrict__ src, const int* __restrict__ dst,
            int* __restrict__ woff, int* __restrict__ eidsrc, int n)
{
    int e = blockIdx.x * blockDim.x + threadIdx.x;
    if (e >= n) return;
    int pos = atomicAdd(&woff[dst[e]], 1);
    eidsrc[pos] = src[e];
}

// ---------------------------------------------------------------------------
// Fused gather + combine (fp16 hW): agg = sum_in hW; h1 = relu(agg+b) + R
// -> Ch fp16 (single split; readout GEMM is 1-term).
// ---------------------------------------------------------------------------
__global__ __launch_bounds__(128)
void gather_combine_k(const __half2* __restrict__ hW2, const int* __restrict__ rowptr,
                      const int* __restrict__ eidsrc, const __half2* __restrict__ R2,
                      const float* __restrict__ bvec,
                      __half2* __restrict__ H2)
{
    int n = blockIdx.x;
    int t = threadIdx.x;
    int start = rowptr[n], end = rowptr[n + 1];
    float ax = 0.f, ay = 0.f, bx = 0.f, by = 0.f;
    int j = start;
    for (; j + 1 < end; j += 2) {
        int s0 = __ldg(eidsrc + j);
        int s1 = __ldg(eidsrc + j + 1);
        float2 v0 = __half22float2(hW2[(size_t)s0 * 128 + t]);
        float2 v1 = __half22float2(hW2[(size_t)s1 * 128 + t]);
        ax += v0.x; ay += v0.y;
        bx += v1.x; by += v1.y;
    }
    if (j < end) {
        int s0 = __ldg(eidsrc + j);
        float2 v0 = __half22float2(hW2[(size_t)s0 * 128 + t]);
        ax += v0.x; ay += v0.y;
    }
    ax += bx; ay += by;
    float2 bb = ((const float2*)bvec)[t];
    float2 r = __half22float2(R2[(size_t)n * 128 + t]);
    float v0 = relu_f(ax + bb.x) + r.x;
    float v1 = relu_f(ay + bb.y) + r.y;
    H2[(size_t)n * 128 + t] = __floats2half2_rn(v0, v1);
}

__global__ void zero_f4(float4* __restrict__ p, int n4)
{
    int i = blockIdx.x * blockDim.x + threadIdx.x;
    int stride = gridDim.x * blockDim.x;
    float4 z = make_float4(0.f, 0.f, 0.f, 0.f);
    for (; i < n4; i += stride) p[i] = z;
}

// gsum[g,:GF] += T[g,:256] @ Ro[256,GF] + cnt[g]*rbo
__global__ __launch_bounds__(256)
void readout_small(const float* __restrict__ T, const float* __restrict__ Ro,
                   const float* __restrict__ rbo, const int* __restrict__ cnt,
                   float* __restrict__ gsum)
{
    __shared__ float sT[DIM];
    int g = blockIdx.x;
    int t = threadIdx.x;
    sT[t] = T[(size_t)g * DIM + t];
    __syncthreads();
    if (t < GF) {
        float a = 0.f;
        #pragma unroll 8
        for (int k = 0; k < DIM; k++) a += sT[k] * Ro[k * GF + t];
        gsum[(size_t)g * GF + t] += a + (float)cnt[g] * rbo[t];
    }
}

__global__ __launch_bounds__(256)
void predict_k(const float* __restrict__ gsum, const float* __restrict__ Wp,
               const float* __restrict__ bp, float* __restrict__ out)
{
    int warp = (int)((blockIdx.x * (size_t)blockDim.x + threadIdx.x) >> 5);
    int lane = threadIdx.x & 31;
    if (warp >= NG) return;
    const float* row = gsum + (size_t)warp * GF;
    float s = 0.f;
    for (int f = lane; f < GF; f += 32) s += row[f] * Wp[f];
    #pragma unroll
    for (int o = 16; o; o >>= 1) s += __shfl_xor_sync(0xffffffffu, s, o);
    if (lane == 0) out[warp] = s + bp[0];
}

// ---------------------------------------------------------------------------
extern "C" void kernel_launch(void* const* d_in, const int* in_sizes, int n_in,
                              void* d_out, int out_size)
{
    const float* nf[2]  = { (const float*)d_in[0], (const float*)d_in[2] };
    const int*   src[2] = { (const int*)d_in[4],   (const int*)d_in[7] };
    const int*   dst[2] = { (const int*)d_in[5],   (const int*)d_in[8] };
    const int*   gid[2] = { (const int*)d_in[6],   (const int*)d_in[9] };
    const float* W[2]   = { (const float*)d_in[10], (const float*)d_in[14] };
    const float* b[2]   = { (const float*)d_in[11], (const float*)d_in[15] };
    const float* Wr[2]  = { (const float*)d_in[12], (const float*)d_in[16] };
    const float* br[2]  = { (const float*)d_in[13], (const float*)d_in[17] };
    const float* Ri[2]  = { (const float*)d_in[18], (const float*)d_in[22] };
    const float* rbi[2] = { (const float*)d_in[19], (const float*)d_in[23] };
    const float* Ro[2]  = { (const float*)d_in[20], (const float*)d_in[24] };
    const float* rbo[2] = { (const float*)d_in[21], (const float*)d_in[25] };
    const float* Wp = (const float*)d_in[26];
    const float* bp = (const float*)d_in[27];
    float* out = (float*)d_out;

    float *T, *gsum;
    __half *hWp, *Rhp, *Ahp, *Alp, *Chp, *WtH;
    int *cnt, *deg, *part, *rowptr, *woff, *bsum, *eidsrc;
    cudaGetSymbolAddress((void**)&hWp, g_hW);
    cudaGetSymbolAddress((void**)&Rhp, g_Rh);
    cudaGetSymbolAddress((void**)&Ahp, g_Ah);
    cudaGetSymbolAddress((void**)&Alp, g_Al);
    cudaGetSymbolAddress((void**)&Chp, g_Ch);
    cudaGetSymbolAddress((void**)&WtH, g_WtH);
    cudaGetSymbolAddress((void**)&T, g_T);
    cudaGetSymbolAddress((void**)&gsum, g_gsum);
    cudaGetSymbolAddress((void**)&cnt, g_cnt);
    cudaGetSymbolAddress((void**)&deg, g_deg);
    cudaGetSymbolAddress((void**)&part, g_part);
    cudaGetSymbolAddress((void**)&rowptr, g_rowptr);
    cudaGetSymbolAddress((void**)&woff, g_woff);
    cudaGetSymbolAddress((void**)&bsum, g_bsum);
    cudaGetSymbolAddress((void**)&eidsrc, g_eidsrc);

    cudaFuncSetAttribute(gemm_tc<M_DUAL>,    cudaFuncAttributeMaxDynamicSharedMemorySize, GEMM_SMEM);
    cudaFuncSetAttribute(gemm_tc<M_READOUT>, cudaFuncAttributeMaxDynamicSharedMemorySize, GEMM_SMEM);

    const int n4 = NN * DIM / 4;
    const int NB = (NN + 1023) / 1024;
    const dim3 gridDual(4, (NN + 127) / 128);   // BN=128, N=512 ([W;Wr])
    const dim3 gridRo(2, (NN + 127) / 128);     // N=256 (Ri)

    // 1: weight transposes (fp16)
    wsplit_all<<<6 * 65536 / 256, 256>>>(W[0], Wr[0], Ri[0], W[1], Wr[1], Ri[1], WtH);
    // 2: zero gsum
    zero_f4<<<64, 256>>>((float4*)gsum, NG * GF / 4);

    for (int k = 0; k < 2; k++) {
        // 3: split h -> Ah/Al
        split_k<<<(n4 + 255) / 256, 256>>>((const float4*)nf[k], (uint2*)Ahp, (uint2*)Alp, n4);
        // 4: dual GEMM -> hW (fp16, 2-term), R (fp16, 1-term)  [ncu slot]
        gemm_tc<M_DUAL><<<gridDual, 256, GEMM_SMEM>>>(Ahp, Alp,
            WtH + (size_t)(k * 3) * 65536, br[k], nullptr, nullptr, hWp, Rhp, NN);
        // 5-10: CSR build
        zero_i<<<(NN + 255) / 256, 256>>>(deg, NN);
        hist_k<<<(NE + 255) / 256, 256>>>(dst[k], deg, NE);
        scan1_k<<<NB, 1024>>>(deg, part, bsum);
        scan2_k<<<1, 32>>>(bsum, NB);
        scan3_k<<<NB, 1024>>>(part, bsum, rowptr, woff);
        fill_k<<<(NE + 255) / 256, 256>>>(src[k], dst[k], woff, eidsrc, NE);
        // 11: fused gather+combine -> Ch (single fp16)
        gather_combine_k<<<NN, 128>>>((const __half2*)hWp, rowptr, eidsrc,
                                      (const __half2*)Rhp, b[k], (__half2*)Chp);
        // 12-13: T = segment_sum(relu(h1@Ri+rbi))  (1-term GEMM)
        zero_f4<<<128, 256>>>((float4*)T, NG * DIM / 4);
        gemm_tc<M_READOUT><<<gridRo, 256, GEMM_SMEM>>>(Chp, nullptr,
            WtH + (size_t)(k * 3 + 2) * 65536, rbi[k], gid[k], T, nullptr, nullptr, NN);
        // 14-16: counts + small readout into gsum
        zero_i<<<2, 256>>>(cnt, NG);
        hist_k<<<(NN + 255) / 256, 256>>>(gid[k], cnt, NN);
        readout_small<<<NG, 256>>>(T, Ro[k], rbo[k], cnt, gsum);
    }

    predict_k<<<(NG * 32 + 255) / 256, 256>>>(gsum, Wp, bp, out);
}

// round 10
// speedup vs baseline: 2.1514x; 1.0459x over previous
#include <cuda_runtime.h>
#include <cuda_fp16.h>
#include <cstdint>

#define NN 50000
#define NE 800000
#define DIM 256
#define GF 200
#define NG 512

// ---------------------------------------------------------------------------
// Scratch (__device__ globals; no allocations allowed)
// ---------------------------------------------------------------------------
__device__ __half g_hW[(size_t)NN * DIM];       // hW (fp16)
__device__ __half g_Rh[(size_t)NN * DIM];       // relu(h@Wr+br) (fp16)
__device__ __half g_Ah[(size_t)NN * DIM];       // h split hi
__device__ __half g_Al[(size_t)NN * DIM];       // h split lo
__device__ __half g_Ch[(size_t)NN * DIM];       // h1 (fp16, single)
__device__ __half g_WtH[6 * DIM * DIM];         // transposed weights fp16
__device__ float g_T[NG * DIM];
__device__ float g_gsum[NG * GF];
// CSR scratch
__device__ int g_deg[NN];
__device__ int g_part[NN];
__device__ int g_rowptr[NN + 1];
__device__ int g_woff[NN];
__device__ int g_bsum[64];
__device__ int g_eidsrc[NE];

enum { M_HW = 0, M_RES = 1, M_RD = 2 };

__device__ __forceinline__ float relu_f(float x) { return x > 0.f ? x : 0.f; }

__device__ __forceinline__ uint32_t smem_u32(const void* p) {
    uint32_t a;
    asm("{ .reg .u64 t; cvta.to.shared.u64 t, %1; cvt.u32.u64 %0, t; }" : "=r"(a) : "l"(p));
    return a;
}
__device__ __forceinline__ uint32_t swz(uint32_t off) { return off ^ ((off >> 3) & 0x70); }
__device__ __forceinline__ void cpa16(uint32_t s, const void* g, int sz) {
    asm volatile("cp.async.cg.shared.global [%0], [%1], 16, %2;" :: "r"(s), "l"(g), "r"(sz) : "memory");
}
__device__ __forceinline__ void ldsm4(uint32_t* r, uint32_t addr) {
    asm volatile("ldmatrix.sync.aligned.m8n8.x4.shared.b16 {%0,%1,%2,%3}, [%4];"
        : "=r"(r[0]), "=r"(r[1]), "=r"(r[2]), "=r"(r[3]) : "r"(addr));
}
__device__ __forceinline__ void mma16816(float* c, const uint32_t* a, const uint32_t* b) {
    asm volatile("mma.sync.aligned.m16n8k16.row.col.f32.f16.f16.f32 "
        "{%0,%1,%2,%3}, {%4,%5,%6,%7}, {%8,%9}, {%0,%1,%2,%3};"
        : "+f"(c[0]), "+f"(c[1]), "+f"(c[2]), "+f"(c[3])
        : "r"(a[0]), "r"(a[1]), "r"(a[2]), "r"(a[3]), "r"(b[0]), "r"(b[1]));
}

// ---------------------------------------------------------------------------
// HMMA GEMM: BM=128, BN=128, BK=64. 256 threads = 8 warps, warp tile 32x64.
// D = Ah*Bh (+ Al*Bh if USELO). Fully compile-time specialized.
// A/B smem double-buffered. 2 CTAs/SM (96KB smem, <=128 regs).
// ---------------------------------------------------------------------------
static const int SM_A = 0;                 // 2buf x 2split x 16KB = 64KB
static const int SM_B = 65536;             // 2buf x 16KB = 32KB
static const int GEMM_SMEM = 98304;        // 96KB

template <int MODE, bool USELO>
__global__ __launch_bounds__(256, 2)
void gemm_tc(const __half* __restrict__ Ah, const __half* __restrict__ Al,
             const __half* __restrict__ Bh,
             const float* __restrict__ bias,   // RES: br ; RD: rbi
             const int* __restrict__ gid,      // RD
             float* __restrict__ outF,         // RD: T
             __half* __restrict__ outH,        // HW: hW ; RES: R
             int M)
{
    extern __shared__ char smem_raw[];
    uint32_t sb = smem_u32(smem_raw);
    const int t = threadIdx.x;
    const int lane = t & 31;
    const int wid = t >> 5;
    const int rowBase = blockIdx.y * 128;
    const int colBase = blockIdx.x * 128;

    const int m0 = (wid & 3) * 32;        // warp m origin (4 m-groups)
    const int n0 = (wid >> 2) * 64;       // warp n origin (2 n-groups)

    const int ar = (lane & 7) + ((lane >> 3) & 1) * 8;
    const int ak = ((lane >> 4) & 1) * 8;
    const int br_ = (lane & 7) + ((lane >> 4) & 1) * 8;
    const int bk = ((lane >> 3) & 1) * 8;

    // loop-invariant swizzled bases (kk folds in via XOR)
    uint32_t aRel[2], bRel[4];
    #pragma unroll
    for (int mt = 0; mt < 2; mt++)
        aRel[mt] = swz((uint32_t)(m0 + mt * 16 + ar) * 128 + ak * 2);
    #pragma unroll
    for (int q = 0; q < 4; q++)
        bRel[q] = swz((uint32_t)(n0 + q * 16 + br_) * 128 + bk * 2);

    const __half* Asrc[2] = { Ah, Al };
    constexpr int nAiter = USELO ? 8 : 4;
    auto loadAB = [&](int c, int buf) {
        #pragma unroll
        for (int i = 0; i < nAiter; i++) {       // A tiles
            int idx = i * 256 + t;
            int split = USELO ? (idx >> 10) : 0;
            int w = idx & 1023;
            int row = w >> 3, seg = w & 7;
            int gr = rowBase + row;
            int ok = gr < M;
            uint32_t sa = sb + SM_A + buf * 32768 + split * 16384 + swz(row * 128 + seg * 16);
            const __half* gp = Asrc[split] + (size_t)(ok ? gr : 0) * 256 + c * 64 + seg * 8;
            cpa16(sa, gp, ok ? 16 : 0);
        }
        #pragma unroll
        for (int i = 0; i < 4; i++) {            // B tile: 1024 16B units
            int idx = i * 256 + t;
            int row = idx >> 3, seg = idx & 7;
            uint32_t sa = sb + SM_B + buf * 16384 + swz(row * 128 + seg * 16);
            const __half* gp = Bh + (size_t)(colBase + row) * 256 + c * 64 + seg * 8;
            cpa16(sa, gp, 16);
        }
    };
    loadAB(0, 0);
    asm volatile("cp.async.commit_group;" ::: "memory");

    float acc[2][8][4] = {};

    #pragma unroll
    for (int c = 0; c < 4; c++) {
        if (c < 3) {
            loadAB(c + 1, (c + 1) & 1);
            asm volatile("cp.async.commit_group;" ::: "memory");
            asm volatile("cp.async.wait_group 1;" ::: "memory");
        } else {
            asm volatile("cp.async.wait_group 0;" ::: "memory");
        }
        __syncthreads();

        uint32_t aH = sb + SM_A + (c & 1) * 32768;
        uint32_t aL = aH + 16384;
        uint32_t bB = sb + SM_B + (c & 1) * 16384;

        #pragma unroll
        for (int kk2 = 0; kk2 < 128; kk2 += 32) {   // kk*2 byte offset
            uint32_t ah[2][4], al[2][4], bh[4][4];
            #pragma unroll
            for (int mt = 0; mt < 2; mt++)
                ldsm4(ah[mt], aH + (aRel[mt] ^ kk2));
            #pragma unroll
            for (int q = 0; q < 4; q++)
                ldsm4(bh[q], bB + (bRel[q] ^ kk2));
            if (USELO) {
                #pragma unroll
                for (int mt = 0; mt < 2; mt++)
                    ldsm4(al[mt], aL + (aRel[mt] ^ kk2));
            }
            #pragma unroll
            for (int mt = 0; mt < 2; mt++)
                #pragma unroll
                for (int nt = 0; nt < 8; nt++)
                    mma16816(acc[mt][nt], ah[mt], &bh[nt >> 1][(nt & 1) * 2]);
            if (USELO) {
                #pragma unroll
                for (int mt = 0; mt < 2; mt++)
                    #pragma unroll
                    for (int nt = 0; nt < 8; nt++)
                        mma16816(acc[mt][nt], al[mt], &bh[nt >> 1][(nt & 1) * 2]);
            }
        }
        __syncthreads();
    }

    if (MODE != M_RD) {
        // ---- fp16 staging (128 x 128, stride 136 halves: conflict-free) ----
        __half* stg = (__half*)smem_raw;
        #pragma unroll
        for (int mt = 0; mt < 2; mt++) {
            #pragma unroll
            for (int nt = 0; nt < 8; nt++) {
                int r = m0 + mt * 16 + (lane >> 2);
                int cc = n0 + nt * 8 + (lane & 3) * 2;
                *(__half2*)&stg[r * 136 + cc] =
                    __floats2half2_rn(acc[mt][nt][0], acc[mt][nt][1]);
                *(__half2*)&stg[(r + 8) * 136 + cc] =
                    __floats2half2_rn(acc[mt][nt][2], acc[mt][nt][3]);
            }
        }
        __syncthreads();
        const int cl = t & 127;
        const int col = colBase + cl;
        if (MODE == M_HW) {
            for (int row = t >> 7; row < 128; row += 2) {
                int gr = rowBase + row;
                if (gr >= M) break;
                outH[(size_t)gr * 256 + col] = stg[row * 136 + cl];
            }
        } else {  // M_RES
            const float bc = bias[col];
            for (int row = t >> 7; row < 128; row += 2) {
                int gr = rowBase + row;
                if (gr >= M) break;
                float f = relu_f(__half2float(stg[row * 136 + cl]) + bc);
                outH[(size_t)gr * 256 + col] = __float2half_rn(f);
            }
        }
    } else {
        // ---- f32 staging + RLE atomics into T ----
        float* stg = (float*)smem_raw;
        #pragma unroll
        for (int mt = 0; mt < 2; mt++) {
            #pragma unroll
            for (int nt = 0; nt < 8; nt++) {
                int r = m0 + mt * 16 + (lane >> 2);
                int cc = n0 + nt * 8 + (lane & 3) * 2;
                stg[r * 129 + cc]           = acc[mt][nt][0];
                stg[r * 129 + cc + 1]       = acc[mt][nt][1];
                stg[(r + 8) * 129 + cc]     = acc[mt][nt][2];
                stg[(r + 8) * 129 + cc + 1] = acc[mt][nt][3];
            }
        }
        __syncthreads();
        const int cl = t & 127;
        const int col = colBase + cl;
        int curg = -1;
        float s = 0.f;
        const float bc = bias[col];
        for (int row = t >> 7; row < 128; row += 2) {
            int gr = rowBase + row;
            if (gr >= M) break;
            float v = relu_f(stg[row * 129 + cl] + bc);
            int g = gid[gr];
            if (g != curg) {
                if (curg >= 0) atomicAdd(&outF[(size_t)curg * 256 + col], s);
                curg = g; s = 0.f;
            }
            s += v;
        }
        if (curg >= 0) atomicAdd(&outF[(size_t)curg * 256 + col], s);
    }
}

// ---------------------------------------------------------------------------
// fp32 -> fp16 hi/lo split (activations)
// ---------------------------------------------------------------------------
__global__ __launch_bounds__(256)
void split_k(const float4* __restrict__ in, uint2* __restrict__ H, uint2* __restrict__ L, int n4)
{
    int i = blockIdx.x * blockDim.x + threadIdx.x;
    if (i >= n4) return;
    float4 f = in[i];
    float xs[4] = { f.x, f.y, f.z, f.w };
    union { __half h[4]; uint2 u; } hh, ll;
    #pragma unroll
    for (int j = 0; j < 4; j++) {
        __half hi = __float2half_rn(xs[j]);
        __half lo = __float2half_rn(xs[j] - __half2float(hi));
        hh.h[j] = hi; ll.h[j] = lo;
    }
    H[i] = hh.u; L[i] = ll.u;
}

// All 6 weight transposes in one launch
__global__ __launch_bounds__(256)
void wsplit_all(const float* __restrict__ w0, const float* __restrict__ w1,
                const float* __restrict__ w2, const float* __restrict__ w3,
                const float* __restrict__ w4, const float* __restrict__ w5,
                __half* __restrict__ H)
{
    int idx = blockIdx.x * 256 + threadIdx.x;
    int m = idx >> 16;
    int rem = idx & 65535;
    int n = rem >> 8, k = rem & 255;
    const float* srcs[6] = { w0, w1, w2, w3, w4, w5 };
    H[idx] = __float2half_rn(srcs[m][k * DIM + n]);
}

// ---------------------------------------------------------------------------
// CSR build
// ---------------------------------------------------------------------------
__global__ void zero_i(int* p, int n)
{
    int i = blockIdx.x * blockDim.x + threadIdx.x;
    if (i < n) p[i] = 0;
}
__global__ __launch_bounds__(256)
void hist_k(const int* __restrict__ idxs, int* __restrict__ cnt, int n)
{
    int i = blockIdx.x * blockDim.x + threadIdx.x;
    if (i < n) atomicAdd(&cnt[idxs[i]], 1);
}
__global__ __launch_bounds__(1024)
void scan1_k(const int* __restrict__ deg, int* __restrict__ part, int* __restrict__ bsum)
{
    __shared__ int s[1024];
    int t = threadIdx.x;
    int idx = blockIdx.x * 1024 + t;
    int v = (idx < NN) ? deg[idx] : 0;
    s[t] = v;
    __syncthreads();
    #pragma unroll
    for (int off = 1; off < 1024; off <<= 1) {
        int x = (t >= off) ? s[t - off] : 0;
        __syncthreads();
        s[t] += x;
        __syncthreads();
    }
    if (idx < NN) part[idx] = s[t] - v;
    if (t == 1023) bsum[blockIdx.x] = s[1023];
}
__global__ void scan2_k(int* bsum, int nb)
{
    if (threadIdx.x == 0) {
        int run = 0;
        for (int i = 0; i < nb; i++) { int v = bsum[i]; bsum[i] = run; run += v; }
    }
}
__global__ __launch_bounds__(1024)
void scan3_k(const int* __restrict__ part, const int* __restrict__ bsum,
             int* __restrict__ rowptr, int* __restrict__ woff)
{
    int idx = blockIdx.x * 1024 + threadIdx.x;
    if (idx < NN) {
        int r = part[idx] + bsum[blockIdx.x];
        rowptr[idx] = r;
        woff[idx] = r;
    }
    if (idx == 0) rowptr[NN] = NE;
}
__global__ __launch_bounds__(256)
void fill_k(const int* __restrict__ src, const int* __restrict__ dst,
            int* __restrict__ woff, int* __restrict__ eidsrc, int n)
{
    int e = blockIdx.x * blockDim.x + threadIdx.x;
    if (e >= n) return;
    int pos = atomicAdd(&woff[dst[e]], 1);
    eidsrc[pos] = src[e];
}

// ---------------------------------------------------------------------------
// Fused gather + combine (fp16 hW): agg = sum_in hW; h1 = relu(agg+b) + R
// -> Ch fp16. 128 threads/node, thread t owns cols {2t, 2t+1}.
// ---------------------------------------------------------------------------
__global__ __launch_bounds__(128)
void gather_combine_k(const __half2* __restrict__ hW2, const int* __restrict__ rowptr,
                      const int* __restrict__ eidsrc, const __half2* __restrict__ R2,
                      const float* __restrict__ bvec,
                      __half2* __restrict__ H2)
{
    int n = blockIdx.x;
    int t = threadIdx.x;
    int start = rowptr[n], end = rowptr[n + 1];
    float ax = 0.f, ay = 0.f, bx = 0.f, by = 0.f;
    int j = start;
    for (; j + 1 < end; j += 2) {
        int s0 = __ldg(eidsrc + j);
        int s1 = __ldg(eidsrc + j + 1);
        float2 v0 = __half22float2(hW2[(size_t)s0 * 128 + t]);
        float2 v1 = __half22float2(hW2[(size_t)s1 * 128 + t]);
        ax += v0.x; ay += v0.y;
        bx += v1.x; by += v1.y;
    }
    if (j < end) {
        int s0 = __ldg(eidsrc + j);
        float2 v0 = __half22float2(hW2[(size_t)s0 * 128 + t]);
        ax += v0.x; ay += v0.y;
    }
    ax += bx; ay += by;
    float2 bb = ((const float2*)bvec)[t];
    float2 r = __half22float2(R2[(size_t)n * 128 + t]);
    float v0 = relu_f(ax + bb.x) + r.x;
    float v1 = relu_f(ay + bb.y) + r.y;
    H2[(size_t)n * 128 + t] = __floats2half2_rn(v0, v1);
}

__global__ void zero_f4(float4* __restrict__ p, int n4)
{
    int i = blockIdx.x * blockDim.x + threadIdx.x;
    int stride = gridDim.x * blockDim.x;
    float4 z = make_float4(0.f, 0.f, 0.f, 0.f);
    for (; i < n4; i += stride) p[i] = z;
}

// gsum[g,:GF] += T[g,:256] @ Ro[256,GF] + cnt(g)*rbo ; cnt via binary search
__global__ __launch_bounds__(256)
void readout_small(const float* __restrict__ T, const float* __restrict__ Ro,
                   const float* __restrict__ rbo, const int* __restrict__ gid,
                   float* __restrict__ gsum)
{
    __shared__ float sT[DIM];
    __shared__ int scnt;
    int g = blockIdx.x;
    int t = threadIdx.x;
    sT[t] = T[(size_t)g * DIM + t];
    if (t == 0) {
        int lo = 0, hi = NN;
        while (lo < hi) { int m = (lo + hi) >> 1; if (gid[m] < g) lo = m + 1; else hi = m; }
        int lo2 = lo, hi2 = NN;
        while (lo2 < hi2) { int m = (lo2 + hi2) >> 1; if (gid[m] <= g) lo2 = m + 1; else hi2 = m; }
        scnt = lo2 - lo;
    }
    __syncthreads();
    if (t < GF) {
        float a = 0.f;
        #pragma unroll 8
        for (int k = 0; k < DIM; k++) a += sT[k] * Ro[k * GF + t];
        gsum[(size_t)g * GF + t] += a + (float)scnt * rbo[t];
    }
}

__global__ __launch_bounds__(256)
void predict_k(const float* __restrict__ gsum, const float* __restrict__ Wp,
               const float* __restrict__ bp, float* __restrict__ out)
{
    int warp = (int)((blockIdx.x * (size_t)blockDim.x + threadIdx.x) >> 5);
    int lane = threadIdx.x & 31;
    if (warp >= NG) return;
    const float* row = gsum + (size_t)warp * GF;
    float s = 0.f;
    for (int f = lane; f < GF; f += 32) s += row[f] * Wp[f];
    #pragma unroll
    for (int o = 16; o; o >>= 1) s += __shfl_xor_sync(0xffffffffu, s, o);
    if (lane == 0) out[warp] = s + bp[0];
}

// ---------------------------------------------------------------------------
extern "C" void kernel_launch(void* const* d_in, const int* in_sizes, int n_in,
                              void* d_out, int out_size)
{
    const float* nf[2]  = { (const float*)d_in[0], (const float*)d_in[2] };
    const int*   src[2] = { (const int*)d_in[4],   (const int*)d_in[7] };
    const int*   dst[2] = { (const int*)d_in[5],   (const int*)d_in[8] };
    const int*   gid[2] = { (const int*)d_in[6],   (const int*)d_in[9] };
    const float* W[2]   = { (const float*)d_in[10], (const float*)d_in[14] };
    const float* b[2]   = { (const float*)d_in[11], (const float*)d_in[15] };
    const float* Wr[2]  = { (const float*)d_in[12], (const float*)d_in[16] };
    const float* br[2]  = { (const float*)d_in[13], (const float*)d_in[17] };
    const float* Ri[2]  = { (const float*)d_in[18], (const float*)d_in[22] };
    const float* rbi[2] = { (const float*)d_in[19], (const float*)d_in[23] };
    const float* Ro[2]  = { (const float*)d_in[20], (const float*)d_in[24] };
    const float* rbo[2] = { (const float*)d_in[21], (const float*)d_in[25] };
    const float* Wp = (const float*)d_in[26];
    const float* bp = (const float*)d_in[27];
    float* out = (float*)d_out;

    float *T, *gsum;
    __half *hWp, *Rhp, *Ahp, *Alp, *Chp, *WtH;
    int *deg, *part, *rowptr, *woff, *bsum, *eidsrc;
    cudaGetSymbolAddress((void**)&hWp, g_hW);
    cudaGetSymbolAddress((void**)&Rhp, g_Rh);
    cudaGetSymbolAddress((void**)&Ahp, g_Ah);
    cudaGetSymbolAddress((void**)&Alp, g_Al);
    cudaGetSymbolAddress((void**)&Chp, g_Ch);
    cudaGetSymbolAddress((void**)&WtH, g_WtH);
    cudaGetSymbolAddress((void**)&T, g_T);
    cudaGetSymbolAddress((void**)&gsum, g_gsum);
    cudaGetSymbolAddress((void**)&deg, g_deg);
    cudaGetSymbolAddress((void**)&part, g_part);
    cudaGetSymbolAddress((void**)&rowptr, g_rowptr);
    cudaGetSymbolAddress((void**)&woff, g_woff);
    cudaGetSymbolAddress((void**)&bsum, g_bsum);
    cudaGetSymbolAddress((void**)&eidsrc, g_eidsrc);

    cudaFuncSetAttribute((const void*)gemm_tc<M_HW,  true >, cudaFuncAttributeMaxDynamicSharedMemorySize, GEMM_SMEM);
    cudaFuncSetAttribute((const void*)gemm_tc<M_RES, false>, cudaFuncAttributeMaxDynamicSharedMemorySize, GEMM_SMEM);
    cudaFuncSetAttribute((const void*)gemm_tc<M_RD,  false>, cudaFuncAttributeMaxDynamicSharedMemorySize, GEMM_SMEM);

    const int n4 = NN * DIM / 4;
    const int NB = (NN + 1023) / 1024;
    const dim3 gridG(2, (NN + 127) / 128);   // BN=128, N=256

    // 1: weight transposes (fp16)
    wsplit_all<<<6 * 65536 / 256, 256>>>(W[0], Wr[0], Ri[0], W[1], Wr[1], Ri[1], WtH);
    // 2: zero gsum
    zero_f4<<<64, 256>>>((float4*)gsum, NG * GF / 4);

    for (int k = 0; k < 2; k++) {
        // 3: split h -> Ah/Al
        split_k<<<(n4 + 255) / 256, 256>>>((const float4*)nf[k], (uint2*)Ahp, (uint2*)Alp, n4);
        // 4: hW GEMM (2-term)  [ncu-profiled slot]
        gemm_tc<M_HW, true><<<gridG, 256, GEMM_SMEM>>>(Ahp, Alp,
            WtH + (size_t)(k * 3 + 0) * 65536, nullptr, nullptr, nullptr, hWp, NN);
        // 5: R GEMM (1-term)
        gemm_tc<M_RES, false><<<gridG, 256, GEMM_SMEM>>>(Ahp, nullptr,
            WtH + (size_t)(k * 3 + 1) * 65536, br[k], nullptr, nullptr, Rhp, NN);
        // 6-10: CSR build
        zero_i<<<(NN + 255) / 256, 256>>>(deg, NN);
        hist_k<<<(NE + 255) / 256, 256>>>(dst[k], deg, NE);
        scan1_k<<<NB, 1024>>>(deg, part, bsum);
        scan2_k<<<1, 32>>>(bsum, NB);
        scan3_k<<<NB, 1024>>>(part, bsum, rowptr, woff);
        fill_k<<<(NE + 255) / 256, 256>>>(src[k], dst[k], woff, eidsrc, NE);
        // 11: fused gather+combine -> Ch (single fp16)
        gather_combine_k<<<NN, 128>>>((const __half2*)hWp, rowptr, eidsrc,
                                      (const __half2*)Rhp, b[k], (__half2*)Chp);
        // 12-13: T = segment_sum(relu(h1@Ri+rbi))  (1-term GEMM)
        zero_f4<<<128, 256>>>((float4*)T, NG * DIM / 4);
        gemm_tc<M_RD, false><<<gridG, 256, GEMM_SMEM>>>(Chp, nullptr,
            WtH + (size_t)(k * 3 + 2) * 65536, rbi[k], gid[k], T, nullptr, NN);
        // 14: small readout into gsum (counts via binary search on sorted gid)
        readout_small<<<NG, 256>>>(T, Ro[k], rbo[k], gid[k], gsum);
    }

    predict_k<<<(NG * 32 + 255) / 256, 256>>>(gsum, Wp, bp, out);
}